// round 8
// baseline (speedup 1.0000x reference)
#include <cuda_runtime.h>
#include <cuda_fp16.h>
#include <cstdint>
#include <math.h>

#define E_DIM 1024
#define C_DIM 1024
#define H_DIM 4096
#define V_DIM 32000
#define L_NUM 6
#define N_TOK 4096
#define LN_EPS 1e-5f

#define NSM_CTAS 296           // persistent grid: 2 CTAs x 148 SMs

// ---------------------------------------------------------------------------
// Static device scratch (no allocation allowed). Weights pre-transposed [N][K].
// ---------------------------------------------------------------------------
__device__ __half g_W1T[(size_t)L_NUM * H_DIM * 2048];     // [L][4096][2048]
__device__ __half g_WgT[(size_t)L_NUM * 3072 * H_DIM];     // [L][3072][4096] (d|f|i)
__device__ __half g_WoutT[(size_t)V_DIM * H_DIM];          // [32000][4096]
__device__ __half g_xc[(size_t)N_TOK * 2048];              // [x | ctx] fp16 GEMM A
__device__ __half g_hidden[(size_t)N_TOK * H_DIM];         // fp16 GEMM A
__device__ float  g_ctx[(size_t)N_TOK * C_DIM];            // fp32 recurrence
__device__ float  g_gates[(size_t)N_TOK * 3072];           // gate pre-activations
__device__ float  g_bg[(size_t)(L_NUM - 1) * 3072];        // concat gate biases

__device__ __forceinline__ uint32_t smem_u32(const void* p) {
    uint32_t a;
    asm("{ .reg .u64 t; cvta.to.shared.u64 t, %1; cvt.u32.u64 %0, t; }" : "=r"(a) : "l"(p));
    return a;
}

// ---------------------------------------------------------------------------
// Persistent GEMM: C[M,N] = act(A[M,K] @ B^T + bias), A row-major fp16 (lda),
// B fp16 [N][K] K-major (ldb). CTA tile 128x128x64, 3-stage cp.async,
// ldmatrix x4 + mma.sync m16n8k16 fp32 accum.
// 128 threads = 4 warps in 2(M) x 2(N), warp tile 64x64. 2 CTAs/SM (96KB).
// Grid = NSM_CTAS; each CTA strides the tile space (m fastest: t&31 / t>>5).
// ---------------------------------------------------------------------------
#define BK 64
#define STAGE_BYTES 32768u     // A 16KB + B 16KB
#define SMEM_GEMM   98304      // 3 stages

__device__ __forceinline__ void cp16(uint32_t d, const void* g) {
    asm volatile("cp.async.cg.shared.global [%0], [%1], 16;\n" :: "r"(d), "l"(g) : "memory");
}

__device__ __forceinline__ void load_stage(
    uint32_t sb, int s, const __half* __restrict__ Ab, int lda,
    const __half* __restrict__ Bb, int ldb, int kt, int tid)
{
    uint32_t base = sb + (uint32_t)s * STAGE_BYTES;
    int k0 = kt * BK;
    #pragma unroll
    for (int j = 0; j < 8; j++) {           // A: 128 rows (M) x 8 chunks
        int i = tid + (j << 7);
        int r = i >> 3, c = i & 7;
        cp16(base + (r << 7) + ((uint32_t)(c ^ (r & 7)) << 4),
             Ab + (size_t)r * lda + k0 + (c << 3));
    }
    #pragma unroll
    for (int j = 0; j < 8; j++) {           // B: 128 rows (N) x 8 chunks
        int i = tid + (j << 7);
        int r = i >> 3, c = i & 7;
        cp16(base + 16384u + (r << 7) + ((uint32_t)(c ^ (r & 7)) << 4),
             Bb + (size_t)r * ldb + k0 + (c << 3));
    }
    asm volatile("cp.async.commit_group;\n" ::: "memory");
}

__global__ __launch_bounds__(128, 2) void gemm_hmma(
    const __half* __restrict__ A, int lda,
    const __half* __restrict__ B, int ldb,
    const float* __restrict__ bias,
    void* __restrict__ Cout, int ldc,
    int K, int mode, int numTiles)   // mode 0: fp32 out; 1: relu -> fp16 out
{
    extern __shared__ __align__(128) char smem[];
    uint32_t sb = smem_u32(smem);
    const int tid = threadIdx.x, lane = tid & 31, warp = tid >> 5;
    const int mW = (warp >> 1) * 64;       // 2 warps in M
    const int nW = (warp & 1) * 64;        // 2 warps in N
    const int KT = K / BK;

    // ldmatrix lane addressing (tile-invariant)
    const int a_row = mW + (lane & 15);            // + mt*16
    const int a_chk = lane >> 4;                   // + ks*2
    const int grp   = lane >> 3;                   // B x4 lane group
    const int b_row_off = (lane & 7) + ((grp >> 1) << 3);   // 0..15
    const int b_chk = grp & 1;                     // k-half within 16

    for (int t = blockIdx.x; t < numTiles; t += NSM_CTAS) {
        const size_t m0 = (size_t)(t & 31) * 128;      // M always 4096 -> 32 m-tiles
        const size_t n0 = (size_t)(t >> 5) * 128;
        const __half* Ab = A + m0 * (size_t)lda;
        const __half* Bb = B + n0 * (size_t)ldb;

        load_stage(sb, 0, Ab, lda, Bb, ldb, 0, tid);
        if (KT > 1) load_stage(sb, 1, Ab, lda, Bb, ldb, 1, tid);

        float acc[4][8][4];
        #pragma unroll
        for (int i = 0; i < 4; i++)
            #pragma unroll
            for (int j = 0; j < 8; j++) {
                acc[i][j][0] = 0.f; acc[i][j][1] = 0.f;
                acc[i][j][2] = 0.f; acc[i][j][3] = 0.f;
            }

        for (int kt = 0; kt < KT; kt++) {
            if (kt + 1 < KT) asm volatile("cp.async.wait_group 1;\n" ::: "memory");
            else             asm volatile("cp.async.wait_group 0;\n" ::: "memory");
            __syncthreads();

            if (kt + 2 < KT)
                load_stage(sb, (kt + 2) % 3, Ab, lda, Bb, ldb, kt + 2, tid);

            uint32_t abase = sb + (uint32_t)(kt % 3) * STAGE_BYTES;
            uint32_t bbase = abase + 16384u;

            #pragma unroll
            for (int ks = 0; ks < 4; ks++) {
                uint32_t af[4][4], bf[8][2];
                #pragma unroll
                for (int mt = 0; mt < 4; mt++) {
                    int r = a_row + mt * 16;
                    int ch = (ks * 2 + a_chk) ^ (r & 7);
                    uint32_t ad = abase + (r << 7) + (ch << 4);
                    asm volatile("ldmatrix.sync.aligned.m8n8.x4.shared.b16 {%0,%1,%2,%3}, [%4];"
                        : "=r"(af[mt][0]), "=r"(af[mt][1]), "=r"(af[mt][2]), "=r"(af[mt][3])
                        : "r"(ad));
                }
                #pragma unroll
                for (int ntp = 0; ntp < 4; ntp++) {
                    int r = nW + ntp * 16 + b_row_off;
                    int ch = (ks * 2 + b_chk) ^ (r & 7);
                    uint32_t bd = bbase + (r << 7) + (ch << 4);
                    asm volatile("ldmatrix.sync.aligned.m8n8.x4.shared.b16 {%0,%1,%2,%3}, [%4];"
                        : "=r"(bf[2*ntp][0]), "=r"(bf[2*ntp][1]),
                          "=r"(bf[2*ntp+1][0]), "=r"(bf[2*ntp+1][1])
                        : "r"(bd));
                }
                #pragma unroll
                for (int mt = 0; mt < 4; mt++)
                    #pragma unroll
                    for (int nt = 0; nt < 8; nt++)
                        asm volatile(
                            "mma.sync.aligned.m16n8k16.row.col.f32.f16.f16.f32 "
                            "{%0,%1,%2,%3}, {%4,%5,%6,%7}, {%8,%9}, {%0,%1,%2,%3};"
                            : "+f"(acc[mt][nt][0]), "+f"(acc[mt][nt][1]),
                              "+f"(acc[mt][nt][2]), "+f"(acc[mt][nt][3])
                            : "r"(af[mt][0]), "r"(af[mt][1]), "r"(af[mt][2]), "r"(af[mt][3]),
                              "r"(bf[nt][0]), "r"(bf[nt][1]));
            }
        }
        __syncthreads();   // protect stage buffers across tile transition

        // Epilogue
        const int er = lane >> 2, ec = (lane & 3) * 2;
        #pragma unroll
        for (int mt = 0; mt < 4; mt++) {
            size_t mA = m0 + mW + mt * 16 + er;
            size_t mB = mA + 8;
            #pragma unroll
            for (int nt = 0; nt < 8; nt++) {
                size_t n = n0 + nW + nt * 8 + ec;
                float b0 = bias[n], b1 = bias[n + 1];
                float v0 = acc[mt][nt][0] + b0;
                float v1 = acc[mt][nt][1] + b1;
                float v2 = acc[mt][nt][2] + b0;
                float v3 = acc[mt][nt][3] + b1;
                if (mode == 0) {
                    float* o = (float*)Cout;
                    *reinterpret_cast<float2*>(o + mA * (size_t)ldc + n) = make_float2(v0, v1);
                    *reinterpret_cast<float2*>(o + mB * (size_t)ldc + n) = make_float2(v2, v3);
                } else {
                    __half* o = (__half*)Cout;
                    v0 = fmaxf(v0, 0.f); v1 = fmaxf(v1, 0.f);
                    v2 = fmaxf(v2, 0.f); v3 = fmaxf(v3, 0.f);
                    *reinterpret_cast<__half2*>(o + mA * (size_t)ldc + n) = __floats2half2_rn(v0, v1);
                    *reinterpret_cast<__half2*>(o + mB * (size_t)ldc + n) = __floats2half2_rn(v2, v3);
                }
            }
        }
    }
}

// ---------------------------------------------------------------------------
// Fast transposing fp32->fp16 convert: out[n][k] = in[k][n], 64x64 tiles.
// ---------------------------------------------------------------------------
__global__ __launch_bounds__(256) void convT2(
    const float* __restrict__ in, __half* __restrict__ out, int K, int N,
    size_t inStride, size_t outStride)
{
    __shared__ float t[64][68];
    in  += (size_t)blockIdx.z * inStride;
    out += (size_t)blockIdx.z * outStride;
    const int n0 = blockIdx.x * 64, k0 = blockIdx.y * 64;
    const int tid = threadIdx.x;
    const int lr = tid >> 4, lc = (tid & 15) << 2;
    #pragma unroll
    for (int it = 0; it < 4; it++) {
        float4 v = *reinterpret_cast<const float4*>(
            in + (size_t)(k0 + lr + it * 16) * N + n0 + lc);
        *reinterpret_cast<float4*>(&t[lr + it * 16][lc]) = v;
    }
    __syncthreads();
    const int n = tid & 63, kq = (tid >> 6) << 4;
    __half h[16];
    #pragma unroll
    for (int i = 0; i < 16; i++) h[i] = __float2half_rn(t[kq + i][n]);
    uint4* o = reinterpret_cast<uint4*>(out + (size_t)(n0 + n) * K + k0 + kq);
    o[0] = reinterpret_cast<uint4*>(h)[0];
    o[1] = reinterpret_cast<uint4*>(h)[1];
}

// ---------------------------------------------------------------------------
// Block reduction (256 threads)
// ---------------------------------------------------------------------------
__device__ __forceinline__ float block_sum(float v) {
    __shared__ float sbuf[8];
    #pragma unroll
    for (int o = 16; o; o >>= 1) v += __shfl_xor_sync(0xffffffffu, v, o);
    if ((threadIdx.x & 31) == 0) sbuf[threadIdx.x >> 5] = v;
    __syncthreads();
    if (threadIdx.x < 32) {
        float s = (threadIdx.x < 8) ? sbuf[threadIdx.x] : 0.f;
        #pragma unroll
        for (int o = 4; o; o >>= 1) s += __shfl_xor_sync(0xffffffffu, s, o);
        if (threadIdx.x == 0) sbuf[0] = s;
    }
    __syncthreads();
    float r = sbuf[0];
    __syncthreads();
    return r;
}

// ---------------------------------------------------------------------------
// Embedding gather + LN -> fp16 x; zero ctx halves
// ---------------------------------------------------------------------------
__global__ __launch_bounds__(256) void embed_ln_kernel(
    const int* __restrict__ ids, const float* __restrict__ emb,
    const float* __restrict__ gw, const float* __restrict__ bw)
{
    int n = blockIdx.x;
    const float* row = emb + (size_t)ids[n] * E_DIM;
    float v[4]; float s = 0.f;
    #pragma unroll
    for (int i = 0; i < 4; i++) { v[i] = row[threadIdx.x + (i << 8)]; s += v[i]; }
    float mean = block_sum(s) * (1.f / E_DIM);
    float q = 0.f;
    #pragma unroll
    for (int i = 0; i < 4; i++) { float d = v[i] - mean; q += d * d; }
    float rstd = rsqrtf(block_sum(q) * (1.f / E_DIM) + LN_EPS);
    __half* out = g_xc + (size_t)n * 2048;
    float* ctx = g_ctx + (size_t)n * C_DIM;
    #pragma unroll
    for (int i = 0; i < 4; i++) {
        int j = threadIdx.x + (i << 8);
        out[j] = __float2half_rn((v[i] - mean) * rstd * gw[j] + bw[j]);
        out[1024 + j] = __float2half_rn(0.f);
        ctx[j] = 0.f;
    }
}

// ---------------------------------------------------------------------------
// Gates -> context update + LN + clip
// ---------------------------------------------------------------------------
__global__ __launch_bounds__(256) void ctx_kernel(
    const float* __restrict__ gw, const float* __restrict__ bw)
{
    int n = blockIdx.x;
    const float* g = g_gates + (size_t)n * 3072;
    float* ctx = g_ctx + (size_t)n * C_DIM;
    __half* cxh = g_xc + (size_t)n * 2048 + 1024;
    float v[4]; float s = 0.f;
    #pragma unroll
    for (int i = 0; i < 4; i++) {
        int j = threadIdx.x + (i << 8);
        float d  = tanhf(g[j]);
        float fg = 1.f / (1.f + expf(-g[1024 + j]));
        float ig = 1.f / (1.f + expf(-g[2048 + j]));
        v[i] = fg * ctx[j] + ig * d;
        s += v[i];
    }
    float mean = block_sum(s) * (1.f / C_DIM);
    float q = 0.f;
    #pragma unroll
    for (int i = 0; i < 4; i++) { float d = v[i] - mean; q += d * d; }
    float rstd = rsqrtf(block_sum(q) * (1.f / C_DIM) + LN_EPS);
    #pragma unroll
    for (int i = 0; i < 4; i++) {
        int j = threadIdx.x + (i << 8);
        float ov = (v[i] - mean) * rstd * gw[j] + bw[j];
        ov = fminf(fmaxf(ov, -10.f), 10.f);
        ctx[j] = ov;
        cxh[j] = __float2half_rn(ov);
    }
}

// all 5 layers' gate biases at once: g_bg[l][3072] = bd|bf|bi of layer l
__global__ void catbias(const float* __restrict__ bd, const float* __restrict__ bf,
                        const float* __restrict__ bi)
{
    int lin = blockIdx.x * 256 + threadIdx.x;      // < 5*3072
    if (lin >= (L_NUM - 1) * 3072) return;
    int l = lin / 3072, j = lin % 3072;
    float v;
    if (j < 1024)      v = bd[(size_t)l * C_DIM + j];
    else if (j < 2048) v = bf[(size_t)l * C_DIM + j - 1024];
    else               v = bi[(size_t)l * C_DIM + j - 2048];
    g_bg[lin] = v;
}

// ---------------------------------------------------------------------------
// Launch
// ---------------------------------------------------------------------------
extern "C" void kernel_launch(void* const* d_in, const int* in_sizes, int n_in,
                              void* d_out, int out_size)
{
    (void)in_sizes; (void)n_in; (void)out_size;
    const int*   ids  = (const int*)d_in[0];
    const float* emb  = (const float*)d_in[1];
    const float* en_g = (const float*)d_in[2];
    const float* en_b = (const float*)d_in[3];
    const float* W1   = (const float*)d_in[4];
    const float* b1   = (const float*)d_in[5];
    const float* Wd   = (const float*)d_in[6];
    const float* bd   = (const float*)d_in[7];
    const float* Wf   = (const float*)d_in[8];
    const float* bf   = (const float*)d_in[9];
    const float* Wi   = (const float*)d_in[10];
    const float* bi   = (const float*)d_in[11];
    const float* lng  = (const float*)d_in[12];
    const float* lnb  = (const float*)d_in[13];
    const float* Wout = (const float*)d_in[14];
    const float* bout = (const float*)d_in[15];
    float* out = (float*)d_out;

    __half *W1T, *WgT, *WoutT, *xc, *hid;
    float *gates, *bg;
    cudaGetSymbolAddress((void**)&W1T, g_W1T);
    cudaGetSymbolAddress((void**)&WgT, g_WgT);
    cudaGetSymbolAddress((void**)&WoutT, g_WoutT);
    cudaGetSymbolAddress((void**)&xc, g_xc);
    cudaGetSymbolAddress((void**)&hid, g_hidden);
    cudaGetSymbolAddress((void**)&gates, g_gates);
    cudaGetSymbolAddress((void**)&bg, g_bg);

    cudaFuncSetAttribute(gemm_hmma, cudaFuncAttributeMaxDynamicSharedMemorySize, SMEM_GEMM);

    // ---- weight conversions (fp32 [K][N] -> fp16 [N][K]) : 5 launches ----
    convT2<<<dim3(H_DIM / 64, 2048 / 64, L_NUM), 256>>>(
        W1, W1T, 2048, H_DIM, (size_t)2048 * H_DIM, (size_t)H_DIM * 2048);
    convT2<<<dim3(C_DIM / 64, H_DIM / 64, L_NUM - 1), 256>>>(
        Wd, WgT + (size_t)0 * 1024 * H_DIM, H_DIM, C_DIM,
        (size_t)H_DIM * C_DIM, (size_t)3072 * H_DIM);
    convT2<<<dim3(C_DIM / 64, H_DIM / 64, L_NUM - 1), 256>>>(
        Wf, WgT + (size_t)1 * 1024 * H_DIM, H_DIM, C_DIM,
        (size_t)H_DIM * C_DIM, (size_t)3072 * H_DIM);
    convT2<<<dim3(C_DIM / 64, H_DIM / 64, L_NUM - 1), 256>>>(
        Wi, WgT + (size_t)2 * 1024 * H_DIM, H_DIM, C_DIM,
        (size_t)H_DIM * C_DIM, (size_t)3072 * H_DIM);
    convT2<<<dim3(V_DIM / 64, H_DIM / 64, 1), 256>>>(
        Wout, WoutT, H_DIM, V_DIM, 0, 0);

    catbias<<<60, 256>>>(bd, bf, bi);
    embed_ln_kernel<<<N_TOK, 256>>>(ids, emb, en_g, en_b);

    const int tilesH = 32 * (H_DIM / 128);    // 1024
    const int tilesG = 32 * (3072 / 128);     // 768
    const int tilesV = 32 * (V_DIM / 128);    // 8000

    for (int l = 0; l < L_NUM; l++) {
        int Keff = (l == 0) ? E_DIM : 2048;
        gemm_hmma<<<NSM_CTAS, 128, SMEM_GEMM>>>(
            xc, 2048, W1T + (size_t)l * H_DIM * 2048, 2048,
            b1 + (size_t)l * H_DIM, hid, H_DIM, Keff, 1, tilesH);

        if (l < L_NUM - 1) {
            gemm_hmma<<<NSM_CTAS, 128, SMEM_GEMM>>>(
                hid, H_DIM, WgT + (size_t)l * 3072 * H_DIM, H_DIM,
                bg + (size_t)l * 3072, gates, 3072, H_DIM, 0, tilesG);
            ctx_kernel<<<N_TOK, 256>>>(lng + (size_t)l * C_DIM, lnb + (size_t)l * C_DIM);
        }
    }

    gemm_hmma<<<NSM_CTAS, 128, SMEM_GEMM>>>(
        hid, H_DIM, WoutT, H_DIM, bout, out, V_DIM, H_DIM, 0, tilesV);
}

// round 9
// speedup vs baseline: 1.0110x; 1.0110x over previous
#include <cuda_runtime.h>
#include <cuda_fp16.h>
#include <cstdint>
#include <math.h>

#define E_DIM 1024
#define C_DIM 1024
#define H_DIM 4096
#define V_DIM 32000
#define L_NUM 6
#define N_TOK 4096
#define LN_EPS 1e-5f

// ---------------------------------------------------------------------------
// Static device scratch (no allocation allowed). Weights pre-transposed [N][K].
// ---------------------------------------------------------------------------
__device__ __half g_W1T[(size_t)L_NUM * H_DIM * 2048];     // [L][4096][2048]
__device__ __half g_WgT[(size_t)L_NUM * 3072 * H_DIM];     // [L][3072][4096] (d|f|i)
__device__ __half g_WoutT[(size_t)V_DIM * H_DIM];          // [32000][4096]
__device__ __half g_xc[(size_t)N_TOK * 2048];              // [x | ctx] fp16 GEMM A
__device__ __half g_hidden[(size_t)N_TOK * H_DIM];         // fp16 GEMM A
__device__ float  g_ctx[(size_t)N_TOK * C_DIM];            // fp32 recurrence
__device__ float  g_gates[(size_t)N_TOK * 3072];           // gate pre-activations
__device__ float  g_bg[(size_t)(L_NUM - 1) * 3072];        // concat gate biases

__device__ __forceinline__ uint32_t smem_u32(const void* p) {
    uint32_t a;
    asm("{ .reg .u64 t; cvta.to.shared.u64 t, %1; cvt.u32.u64 %0, t; }" : "=r"(a) : "l"(p));
    return a;
}

// ---------------------------------------------------------------------------
// GEMM: C[M,N] = act(A[M,K] @ B^T + bias), A row-major fp16 (lda),
// B fp16 [N][K] K-major (ldb). CTA tile 128x128x64, 3-stage cp.async,
// ldmatrix x4 + mma.sync m16n8k16 fp32 accum.
// 128 threads = 4 warps in 2(M) x 2(N), warp tile 64x64. 2 CTAs/SM (96KB).
// ---------------------------------------------------------------------------
#define BK 64
#define STAGE_BYTES 32768u     // A 16KB + B 16KB
#define SMEM_GEMM   98304      // 3 stages

__device__ __forceinline__ void cp16(uint32_t d, const void* g) {
    asm volatile("cp.async.cg.shared.global [%0], [%1], 16;\n" :: "r"(d), "l"(g) : "memory");
}

__device__ __forceinline__ void load_stage(
    uint32_t sb, int s, const __half* __restrict__ Ab, int lda,
    const __half* __restrict__ Bb, int ldb, int kt, int tid)
{
    uint32_t base = sb + (uint32_t)s * STAGE_BYTES;
    int k0 = kt * BK;
    #pragma unroll
    for (int j = 0; j < 8; j++) {           // A: 128 rows (M) x 8 chunks
        int i = tid + (j << 7);
        int r = i >> 3, c = i & 7;
        cp16(base + (r << 7) + ((uint32_t)(c ^ (r & 7)) << 4),
             Ab + (size_t)r * lda + k0 + (c << 3));
    }
    #pragma unroll
    for (int j = 0; j < 8; j++) {           // B: 128 rows (N) x 8 chunks
        int i = tid + (j << 7);
        int r = i >> 3, c = i & 7;
        cp16(base + 16384u + (r << 7) + ((uint32_t)(c ^ (r & 7)) << 4),
             Bb + (size_t)r * ldb + k0 + (c << 3));
    }
    asm volatile("cp.async.commit_group;\n" ::: "memory");
}

__global__ __launch_bounds__(128, 2) void gemm_hmma(
    const __half* __restrict__ A, int lda,
    const __half* __restrict__ B, int ldb,
    const float* __restrict__ bias,
    void* __restrict__ Cout, int ldc,
    int K, int mode)   // mode 0: fp32 out; 1: relu -> fp16 out
{
    extern __shared__ __align__(128) char smem[];
    uint32_t sb = smem_u32(smem);
    const int tid = threadIdx.x, lane = tid & 31, warp = tid >> 5;
    const int mW = (warp >> 1) * 64;       // 2 warps in M
    const int nW = (warp & 1) * 64;        // 2 warps in N

    const size_t m0 = (size_t)blockIdx.x * 128;
    const size_t n0 = (size_t)blockIdx.y * 128;
    const __half* Ab = A + m0 * (size_t)lda;
    const __half* Bb = B + n0 * (size_t)ldb;

    const int KT = K / BK;

    load_stage(sb, 0, Ab, lda, Bb, ldb, 0, tid);
    if (KT > 1) load_stage(sb, 1, Ab, lda, Bb, ldb, 1, tid);

    float acc[4][8][4];
    #pragma unroll
    for (int i = 0; i < 4; i++)
        #pragma unroll
        for (int j = 0; j < 8; j++) {
            acc[i][j][0] = 0.f; acc[i][j][1] = 0.f;
            acc[i][j][2] = 0.f; acc[i][j][3] = 0.f;
        }

    // ldmatrix lane addressing
    const int a_row = mW + (lane & 15);            // + mt*16
    const int a_chk = lane >> 4;                   // + ks*2
    const int grp   = lane >> 3;                   // B x4 lane group
    const int b_row_off = (lane & 7) + ((grp >> 1) << 3);   // 0..15
    const int b_chk = grp & 1;                     // k-half within 16

    for (int kt = 0; kt < KT; kt++) {
        if (kt + 1 < KT) asm volatile("cp.async.wait_group 1;\n" ::: "memory");
        else             asm volatile("cp.async.wait_group 0;\n" ::: "memory");
        __syncthreads();   // single barrier per iteration (orders buffer reuse too)

        if (kt + 2 < KT)
            load_stage(sb, (kt + 2) % 3, Ab, lda, Bb, ldb, kt + 2, tid);

        uint32_t abase = sb + (uint32_t)(kt % 3) * STAGE_BYTES;
        uint32_t bbase = abase + 16384u;

        #pragma unroll
        for (int ks = 0; ks < 4; ks++) {
            uint32_t af[4][4], bf[8][2];
            #pragma unroll
            for (int mt = 0; mt < 4; mt++) {
                int r = a_row + mt * 16;
                int ch = (ks * 2 + a_chk) ^ (r & 7);
                uint32_t ad = abase + (r << 7) + (ch << 4);
                asm volatile("ldmatrix.sync.aligned.m8n8.x4.shared.b16 {%0,%1,%2,%3}, [%4];"
                    : "=r"(af[mt][0]), "=r"(af[mt][1]), "=r"(af[mt][2]), "=r"(af[mt][3])
                    : "r"(ad));
            }
            #pragma unroll
            for (int ntp = 0; ntp < 4; ntp++) {    // pair of 8-col n-groups
                int r = nW + ntp * 16 + b_row_off;
                int ch = (ks * 2 + b_chk) ^ (r & 7);
                uint32_t bd = bbase + (r << 7) + (ch << 4);
                asm volatile("ldmatrix.sync.aligned.m8n8.x4.shared.b16 {%0,%1,%2,%3}, [%4];"
                    : "=r"(bf[2*ntp][0]), "=r"(bf[2*ntp][1]),
                      "=r"(bf[2*ntp+1][0]), "=r"(bf[2*ntp+1][1])
                    : "r"(bd));
            }
            #pragma unroll
            for (int mt = 0; mt < 4; mt++)
                #pragma unroll
                for (int nt = 0; nt < 8; nt++)
                    asm volatile(
                        "mma.sync.aligned.m16n8k16.row.col.f32.f16.f16.f32 "
                        "{%0,%1,%2,%3}, {%4,%5,%6,%7}, {%8,%9}, {%0,%1,%2,%3};"
                        : "+f"(acc[mt][nt][0]), "+f"(acc[mt][nt][1]),
                          "+f"(acc[mt][nt][2]), "+f"(acc[mt][nt][3])
                        : "r"(af[mt][0]), "r"(af[mt][1]), "r"(af[mt][2]), "r"(af[mt][3]),
                          "r"(bf[nt][0]), "r"(bf[nt][1]));
        }
    }

    // Epilogue
    const int er = lane >> 2, ec = (lane & 3) * 2;
    #pragma unroll
    for (int mt = 0; mt < 4; mt++) {
        size_t mA = m0 + mW + mt * 16 + er;
        size_t mB = mA + 8;
        #pragma unroll
        for (int nt = 0; nt < 8; nt++) {
            size_t n = n0 + nW + nt * 8 + ec;
            float b0 = bias[n], b1 = bias[n + 1];
            float v0 = acc[mt][nt][0] + b0;
            float v1 = acc[mt][nt][1] + b1;
            float v2 = acc[mt][nt][2] + b0;
            float v3 = acc[mt][nt][3] + b1;
            if (mode == 0) {
                float* o = (float*)Cout;
                *reinterpret_cast<float2*>(o + mA * (size_t)ldc + n) = make_float2(v0, v1);
                *reinterpret_cast<float2*>(o + mB * (size_t)ldc + n) = make_float2(v2, v3);
            } else {
                __half* o = (__half*)Cout;
                v0 = fmaxf(v0, 0.f); v1 = fmaxf(v1, 0.f);
                v2 = fmaxf(v2, 0.f); v3 = fmaxf(v3, 0.f);
                *reinterpret_cast<__half2*>(o + mA * (size_t)ldc + n) = __floats2half2_rn(v0, v1);
                *reinterpret_cast<__half2*>(o + mB * (size_t)ldc + n) = __floats2half2_rn(v2, v3);
            }
        }
    }
}

// ---------------------------------------------------------------------------
// Transposing fp32->fp16 convert core: out[n][k] = in[k][n], 64x64 tile.
// ---------------------------------------------------------------------------
__device__ __forceinline__ void convT_core(
    const float* __restrict__ in, __half* __restrict__ out, int K, int N,
    int n0, int k0, int tid)
{
    __shared__ float t[64][68];
    const int lr = tid >> 4, lc = (tid & 15) << 2;
    #pragma unroll
    for (int it = 0; it < 4; it++) {
        float4 v = *reinterpret_cast<const float4*>(
            in + (size_t)(k0 + lr + it * 16) * N + n0 + lc);
        *reinterpret_cast<float4*>(&t[lr + it * 16][lc]) = v;
    }
    __syncthreads();
    const int n = tid & 63, kq = (tid >> 6) << 4;
    __half h[16];
    #pragma unroll
    for (int i = 0; i < 16; i++) h[i] = __float2half_rn(t[kq + i][n]);
    uint4* o = reinterpret_cast<uint4*>(out + (size_t)(n0 + n) * K + k0 + kq);
    o[0] = reinterpret_cast<uint4*>(h)[0];
    o[1] = reinterpret_cast<uint4*>(h)[1];
}

__global__ __launch_bounds__(256) void convT2(
    const float* __restrict__ in, __half* __restrict__ out, int K, int N,
    size_t inStride, size_t outStride)
{
    convT_core(in + (size_t)blockIdx.z * inStride,
               out + (size_t)blockIdx.z * outStride,
               K, N, blockIdx.x * 64, blockIdx.y * 64, threadIdx.x);
}

// All gate weights in one launch: z in [0, 15) -> layer z/3, gate z%3.
__global__ __launch_bounds__(256) void conv_gatesT(
    const float* __restrict__ Wd, const float* __restrict__ Wf,
    const float* __restrict__ Wi)
{
    int z = blockIdx.z, l = z / 3, gI = z - l * 3;
    const float* in = (gI == 0 ? Wd : (gI == 1 ? Wf : Wi)) + (size_t)l * H_DIM * C_DIM;
    __half* out = g_WgT + ((size_t)l * 3072 + (size_t)gI * 1024) * H_DIM;
    convT_core(in, out, H_DIM, C_DIM, blockIdx.x * 64, blockIdx.y * 64, threadIdx.x);
}

// ---------------------------------------------------------------------------
// Block reduction (256 threads)
// ---------------------------------------------------------------------------
__device__ __forceinline__ float block_sum(float v) {
    __shared__ float sbuf[8];
    #pragma unroll
    for (int o = 16; o; o >>= 1) v += __shfl_xor_sync(0xffffffffu, v, o);
    if ((threadIdx.x & 31) == 0) sbuf[threadIdx.x >> 5] = v;
    __syncthreads();
    if (threadIdx.x < 32) {
        float s = (threadIdx.x < 8) ? sbuf[threadIdx.x] : 0.f;
        #pragma unroll
        for (int o = 4; o; o >>= 1) s += __shfl_xor_sync(0xffffffffu, s, o);
        if (threadIdx.x == 0) sbuf[0] = s;
    }
    __syncthreads();
    float r = sbuf[0];
    __syncthreads();
    return r;
}

// ---------------------------------------------------------------------------
// Embedding gather + LN -> fp16 x; zero ctx halves
// ---------------------------------------------------------------------------
__global__ __launch_bounds__(256) void embed_ln_kernel(
    const int* __restrict__ ids, const float* __restrict__ emb,
    const float* __restrict__ gw, const float* __restrict__ bw)
{
    int n = blockIdx.x;
    const float* row = emb + (size_t)ids[n] * E_DIM;
    float v[4]; float s = 0.f;
    #pragma unroll
    for (int i = 0; i < 4; i++) { v[i] = row[threadIdx.x + (i << 8)]; s += v[i]; }
    float mean = block_sum(s) * (1.f / E_DIM);
    float q = 0.f;
    #pragma unroll
    for (int i = 0; i < 4; i++) { float d = v[i] - mean; q += d * d; }
    float rstd = rsqrtf(block_sum(q) * (1.f / E_DIM) + LN_EPS);
    __half* out = g_xc + (size_t)n * 2048;
    float* ctx = g_ctx + (size_t)n * C_DIM;
    #pragma unroll
    for (int i = 0; i < 4; i++) {
        int j = threadIdx.x + (i << 8);
        out[j] = __float2half_rn((v[i] - mean) * rstd * gw[j] + bw[j]);
        out[1024 + j] = __float2half_rn(0.f);
        ctx[j] = 0.f;
    }
}

// ---------------------------------------------------------------------------
// Gates -> context update + LN + clip
// ---------------------------------------------------------------------------
__global__ __launch_bounds__(256) void ctx_kernel(
    const float* __restrict__ gw, const float* __restrict__ bw)
{
    int n = blockIdx.x;
    const float* g = g_gates + (size_t)n * 3072;
    float* ctx = g_ctx + (size_t)n * C_DIM;
    __half* cxh = g_xc + (size_t)n * 2048 + 1024;
    float v[4]; float s = 0.f;
    #pragma unroll
    for (int i = 0; i < 4; i++) {
        int j = threadIdx.x + (i << 8);
        float d  = tanhf(g[j]);
        float fg = 1.f / (1.f + expf(-g[1024 + j]));
        float ig = 1.f / (1.f + expf(-g[2048 + j]));
        v[i] = fg * ctx[j] + ig * d;
        s += v[i];
    }
    float mean = block_sum(s) * (1.f / C_DIM);
    float q = 0.f;
    #pragma unroll
    for (int i = 0; i < 4; i++) { float d = v[i] - mean; q += d * d; }
    float rstd = rsqrtf(block_sum(q) * (1.f / C_DIM) + LN_EPS);
    #pragma unroll
    for (int i = 0; i < 4; i++) {
        int j = threadIdx.x + (i << 8);
        float ov = (v[i] - mean) * rstd * gw[j] + bw[j];
        ov = fminf(fmaxf(ov, -10.f), 10.f);
        ctx[j] = ov;
        cxh[j] = __float2half_rn(ov);
    }
}

// all 5 layers' gate biases at once: g_bg[l][3072] = bd|bf|bi of layer l
__global__ void catbias(const float* __restrict__ bd, const float* __restrict__ bf,
                        const float* __restrict__ bi)
{
    int lin = blockIdx.x * 256 + threadIdx.x;      // < 5*3072
    if (lin >= (L_NUM - 1) * 3072) return;
    int l = lin / 3072, j = lin % 3072;
    float v;
    if (j < 1024)      v = bd[(size_t)l * C_DIM + j];
    else if (j < 2048) v = bf[(size_t)l * C_DIM + j - 1024];
    else               v = bi[(size_t)l * C_DIM + j - 2048];
    g_bg[lin] = v;
}

// ---------------------------------------------------------------------------
// Launch: Wout conversion overlapped on a side stream (fork-join events).
// ---------------------------------------------------------------------------
extern "C" void kernel_launch(void* const* d_in, const int* in_sizes, int n_in,
                              void* d_out, int out_size)
{
    (void)in_sizes; (void)n_in; (void)out_size;
    const int*   ids  = (const int*)d_in[0];
    const float* emb  = (const float*)d_in[1];
    const float* en_g = (const float*)d_in[2];
    const float* en_b = (const float*)d_in[3];
    const float* W1   = (const float*)d_in[4];
    const float* b1   = (const float*)d_in[5];
    const float* Wd   = (const float*)d_in[6];
    const float* bd   = (const float*)d_in[7];
    const float* Wf   = (const float*)d_in[8];
    const float* bf   = (const float*)d_in[9];
    const float* Wi   = (const float*)d_in[10];
    const float* bi   = (const float*)d_in[11];
    const float* lng  = (const float*)d_in[12];
    const float* lnb  = (const float*)d_in[13];
    const float* Wout = (const float*)d_in[14];
    const float* bout = (const float*)d_in[15];
    float* out = (float*)d_out;

    __half *W1T, *WoutT, *WgT, *xc, *hid;
    float *gates, *bg;
    cudaGetSymbolAddress((void**)&W1T, g_W1T);
    cudaGetSymbolAddress((void**)&WgT, g_WgT);
    cudaGetSymbolAddress((void**)&WoutT, g_WoutT);
    cudaGetSymbolAddress((void**)&xc, g_xc);
    cudaGetSymbolAddress((void**)&hid, g_hidden);
    cudaGetSymbolAddress((void**)&gates, g_gates);
    cudaGetSymbolAddress((void**)&bg, g_bg);

    cudaFuncSetAttribute(gemm_hmma, cudaFuncAttributeMaxDynamicSharedMemorySize, SMEM_GEMM);

    static cudaStream_t s2 = nullptr;
    static cudaEvent_t evFork = nullptr, evJoin = nullptr;
    if (s2 == nullptr) {
        cudaStreamCreateWithFlags(&s2, cudaStreamNonBlocking);
        cudaEventCreateWithFlags(&evFork, cudaEventDisableTiming);
        cudaEventCreateWithFlags(&evJoin, cudaEventDisableTiming);
    }

    // ---- serial conversions needed early ----
    convT2<<<dim3(H_DIM / 64, 2048 / 64, L_NUM), 256>>>(
        W1, W1T, 2048, H_DIM, (size_t)2048 * H_DIM, (size_t)H_DIM * 2048);
    conv_gatesT<<<dim3(C_DIM / 64, H_DIM / 64, 3 * (L_NUM - 1)), 256>>>(Wd, Wf, Wi);
    catbias<<<60, 256>>>(bd, bf, bi);
    embed_ln_kernel<<<N_TOK, 256>>>(ids, emb, en_g, en_b);

    // ---- fork: Wout conversion overlaps the whole layer stack ----
    cudaEventRecord(evFork, 0);
    cudaStreamWaitEvent(s2, evFork, 0);
    convT2<<<dim3(V_DIM / 64, H_DIM / 64, 1), 256, 0, s2>>>(
        Wout, WoutT, H_DIM, V_DIM, 0, 0);
    cudaEventRecord(evJoin, s2);

    dim3 gH(N_TOK / 128, H_DIM / 128);   // (32, 32)
    dim3 gG(N_TOK / 128, 3072 / 128);    // (32, 24)
    dim3 gV(N_TOK / 128, V_DIM / 128);   // (32, 250)

    for (int l = 0; l < L_NUM; l++) {
        int Keff = (l == 0) ? E_DIM : 2048;
        gemm_hmma<<<gH, 128, SMEM_GEMM>>>(
            xc, 2048, W1T + (size_t)l * H_DIM * 2048, 2048,
            b1 + (size_t)l * H_DIM, hid, H_DIM, Keff, 1);

        if (l < L_NUM - 1) {
            gemm_hmma<<<gG, 128, SMEM_GEMM>>>(
                hid, H_DIM, WgT + (size_t)l * 3072 * H_DIM, H_DIM,
                bg + (size_t)l * 3072, gates, 3072, H_DIM, 0);
            ctx_kernel<<<N_TOK, 256>>>(lng + (size_t)l * C_DIM, lnb + (size_t)l * C_DIM);
        }
    }

    // ---- join: head GEMM needs WoutT ----
    cudaStreamWaitEvent(0, evJoin, 0);
    gemm_hmma<<<gV, 128, SMEM_GEMM>>>(hid, H_DIM, WoutT, H_DIM, bout, out, V_DIM, H_DIM, 0);
}

// round 12
// speedup vs baseline: 1.0281x; 1.0169x over previous
#include <cuda_runtime.h>
#include <cuda_fp16.h>
#include <cstdint>
#include <math.h>

#define E_DIM 1024
#define C_DIM 1024
#define H_DIM 4096
#define V_DIM 32000
#define L_NUM 6
#define N_TOK 4096
#define LN_EPS 1e-5f

// ---------------------------------------------------------------------------
// Static device scratch (no allocation allowed). Weights pre-transposed [N][K].
// ---------------------------------------------------------------------------
__device__ __half g_W1T[(size_t)L_NUM * H_DIM * 2048];     // [L][4096][2048]
__device__ __half g_WgT[(size_t)L_NUM * 3072 * H_DIM];     // [L][3072][4096] (d|f|i)
__device__ __half g_WoutT[(size_t)V_DIM * H_DIM];          // [32000][4096]
__device__ __half g_xc[(size_t)N_TOK * 2048];              // [x | ctx] fp16 GEMM A
__device__ __half g_hidden[(size_t)N_TOK * H_DIM];         // fp16 GEMM A
__device__ float  g_ctx[(size_t)N_TOK * C_DIM];            // fp32 recurrence
__device__ float  g_gates[(size_t)N_TOK * 3072];           // gate pre-activations
__device__ float  g_bg[(size_t)(L_NUM - 1) * 3072];        // concat gate biases

__device__ __forceinline__ uint32_t smem_u32(const void* p) {
    uint32_t a;
    asm("{ .reg .u64 t; cvta.to.shared.u64 t, %1; cvt.u32.u64 %0, t; }" : "=r"(a) : "l"(p));
    return a;
}

// ---------------------------------------------------------------------------
// GEMM: C[M,N] = act(A[M,K] @ B^T + bias), A row-major fp16 (lda),
// B fp16 [N][K] K-major (ldb). CTA tile 128x128x64, 3-stage cp.async,
// ldmatrix x4 + mma.sync m16n8k16 fp32 accum.
// 128 threads = 4 warps in 2(M) x 2(N), warp tile 64x64. 2 CTAs/SM (96KB).
// ---------------------------------------------------------------------------
#define BK 64
#define STAGE_BYTES 32768u     // A 16KB + B 16KB
#define SMEM_GEMM   98304      // 3 stages

__device__ __forceinline__ void cp16(uint32_t d, const void* g) {
    asm volatile("cp.async.cg.shared.global [%0], [%1], 16;\n" :: "r"(d), "l"(g) : "memory");
}

__device__ __forceinline__ void load_stage(
    uint32_t sb, int s, const __half* __restrict__ Ab, int lda,
    const __half* __restrict__ Bb, int ldb, int kt, int tid)
{
    uint32_t base = sb + (uint32_t)s * STAGE_BYTES;
    int k0 = kt * BK;
    #pragma unroll
    for (int j = 0; j < 8; j++) {           // A: 128 rows (M) x 8 chunks
        int i = tid + (j << 7);
        int r = i >> 3, c = i & 7;
        cp16(base + (r << 7) + ((uint32_t)(c ^ (r & 7)) << 4),
             Ab + (size_t)r * lda + k0 + (c << 3));
    }
    #pragma unroll
    for (int j = 0; j < 8; j++) {           // B: 128 rows (N) x 8 chunks
        int i = tid + (j << 7);
        int r = i >> 3, c = i & 7;
        cp16(base + 16384u + (r << 7) + ((uint32_t)(c ^ (r & 7)) << 4),
             Bb + (size_t)r * ldb + k0 + (c << 3));
    }
    asm volatile("cp.async.commit_group;\n" ::: "memory");
}

__global__ __launch_bounds__(128, 2) void gemm_hmma(
    const __half* __restrict__ A, int lda,
    const __half* __restrict__ B, int ldb,
    const float* __restrict__ bias,
    void* __restrict__ Cout, int ldc,
    int K, int mode)   // mode 0: fp32 out; 1: relu -> fp16 out
{
    extern __shared__ __align__(128) char smem[];
    uint32_t sb = smem_u32(smem);
    const int tid = threadIdx.x, lane = tid & 31, warp = tid >> 5;
    const int mW = (warp >> 1) * 64;       // 2 warps in M
    const int nW = (warp & 1) * 64;        // 2 warps in N

    const size_t m0 = (size_t)blockIdx.x * 128;
    const size_t n0 = (size_t)blockIdx.y * 128;
    const __half* Ab = A + m0 * (size_t)lda;
    const __half* Bb = B + n0 * (size_t)ldb;

    const int KT = K / BK;

    load_stage(sb, 0, Ab, lda, Bb, ldb, 0, tid);
    if (KT > 1) load_stage(sb, 1, Ab, lda, Bb, ldb, 1, tid);

    float acc[4][8][4];
    #pragma unroll
    for (int i = 0; i < 4; i++)
        #pragma unroll
        for (int j = 0; j < 8; j++) {
            acc[i][j][0] = 0.f; acc[i][j][1] = 0.f;
            acc[i][j][2] = 0.f; acc[i][j][3] = 0.f;
        }

    // ldmatrix lane addressing
    const int a_row = mW + (lane & 15);            // + mt*16
    const int a_chk = lane >> 4;                   // + ks*2
    const int grp   = lane >> 3;                   // B x4 lane group
    const int b_row_off = (lane & 7) + ((grp >> 1) << 3);   // 0..15
    const int b_chk = grp & 1;                     // k-half within 16

    for (int kt = 0; kt < KT; kt++) {
        if (kt + 1 < KT) asm volatile("cp.async.wait_group 1;\n" ::: "memory");
        else             asm volatile("cp.async.wait_group 0;\n" ::: "memory");
        __syncthreads();   // single barrier per iteration (orders buffer reuse too)

        if (kt + 2 < KT)
            load_stage(sb, (kt + 2) % 3, Ab, lda, Bb, ldb, kt + 2, tid);

        uint32_t abase = sb + (uint32_t)(kt % 3) * STAGE_BYTES;
        uint32_t bbase = abase + 16384u;

        #pragma unroll
        for (int ks = 0; ks < 4; ks++) {
            uint32_t af[4][4], bf[8][2];
            #pragma unroll
            for (int mt = 0; mt < 4; mt++) {
                int r = a_row + mt * 16;
                int ch = (ks * 2 + a_chk) ^ (r & 7);
                uint32_t ad = abase + (r << 7) + (ch << 4);
                asm volatile("ldmatrix.sync.aligned.m8n8.x4.shared.b16 {%0,%1,%2,%3}, [%4];"
                    : "=r"(af[mt][0]), "=r"(af[mt][1]), "=r"(af[mt][2]), "=r"(af[mt][3])
                    : "r"(ad));
            }
            #pragma unroll
            for (int ntp = 0; ntp < 4; ntp++) {    // pair of 8-col n-groups
                int r = nW + ntp * 16 + b_row_off;
                int ch = (ks * 2 + b_chk) ^ (r & 7);
                uint32_t bd = bbase + (r << 7) + (ch << 4);
                asm volatile("ldmatrix.sync.aligned.m8n8.x4.shared.b16 {%0,%1,%2,%3}, [%4];"
                    : "=r"(bf[2*ntp][0]), "=r"(bf[2*ntp][1]),
                      "=r"(bf[2*ntp+1][0]), "=r"(bf[2*ntp+1][1])
                    : "r"(bd));
            }
            #pragma unroll
            for (int mt = 0; mt < 4; mt++)
                #pragma unroll
                for (int nt = 0; nt < 8; nt++)
                    asm volatile(
                        "mma.sync.aligned.m16n8k16.row.col.f32.f16.f16.f32 "
                        "{%0,%1,%2,%3}, {%4,%5,%6,%7}, {%8,%9}, {%0,%1,%2,%3};"
                        : "+f"(acc[mt][nt][0]), "+f"(acc[mt][nt][1]),
                          "+f"(acc[mt][nt][2]), "+f"(acc[mt][nt][3])
                        : "r"(af[mt][0]), "r"(af[mt][1]), "r"(af[mt][2]), "r"(af[mt][3]),
                          "r"(bf[nt][0]), "r"(bf[nt][1]));
        }
    }

    // Epilogue
    const int er = lane >> 2, ec = (lane & 3) * 2;
    #pragma unroll
    for (int mt = 0; mt < 4; mt++) {
        size_t mA = m0 + mW + mt * 16 + er;
        size_t mB = mA + 8;
        #pragma unroll
        for (int nt = 0; nt < 8; nt++) {
            size_t n = n0 + nW + nt * 8 + ec;
            float b0 = bias[n], b1 = bias[n + 1];
            float v0 = acc[mt][nt][0] + b0;
            float v1 = acc[mt][nt][1] + b1;
            float v2 = acc[mt][nt][2] + b0;
            float v3 = acc[mt][nt][3] + b1;
            if (mode == 0) {
                float* o = (float*)Cout;
                *reinterpret_cast<float2*>(o + mA * (size_t)ldc + n) = make_float2(v0, v1);
                *reinterpret_cast<float2*>(o + mB * (size_t)ldc + n) = make_float2(v2, v3);
            } else {
                __half* o = (__half*)Cout;
                v0 = fmaxf(v0, 0.f); v1 = fmaxf(v1, 0.f);
                v2 = fmaxf(v2, 0.f); v3 = fmaxf(v3, 0.f);
                *reinterpret_cast<__half2*>(o + mA * (size_t)ldc + n) = __floats2half2_rn(v0, v1);
                *reinterpret_cast<__half2*>(o + mB * (size_t)ldc + n) = __floats2half2_rn(v2, v3);
            }
        }
    }
}

// ---------------------------------------------------------------------------
// Write-coalesced transposing fp32->fp16 convert: out[n][k] = in[k][n].
// 64x64 tile, 256 threads, XOR-swizzled smem t[64][64] (no padding):
// element (k,n) lives at col 4*((n>>2)^((k>>3)&7)) + (n&3).
//  - Phase-1 float4 stores: rows are 256B -> always 16B aligned (fixes the
//    R10/R11 misaligned STS.128 trap caused by pad 65).
//  - Phase-2 reads: lanes (g=lane&7 k-group, rgrp=lane>>3) hit banks
//    4*((q^g)&7)+rgrp -> all 32 distinct, conflict-free.
//  - Phase-2 global stores: each warp writes 4 n-rows x 128B contiguous
//    (4 L1 lines/STG.128 vs 32 in the old layout).
// ---------------------------------------------------------------------------
__device__ __forceinline__ void convT_core(
    const float* __restrict__ in, __half* __restrict__ out, int K, int N,
    int n0, int k0, int tid)
{
    __shared__ float t[64][64];
    const int lr = tid >> 4, cg = tid & 15;        // k-row base, n col-group
    #pragma unroll
    for (int it = 0; it < 4; it++) {
        int k = lr + it * 16;
        float4 v = *reinterpret_cast<const float4*>(
            in + (size_t)(k0 + k) * N + n0 + (cg << 2));
        int cgs = cg ^ ((k >> 3) & 7);
        *reinterpret_cast<float4*>(&t[k][cgs << 2]) = v;
    }
    __syncthreads();
    const int w = tid >> 5, lane = tid & 31;
    const int g = lane & 7, rgrp = lane >> 3;
    const int koff = g << 3;
    #pragma unroll
    for (int it2 = 0; it2 < 2; it2++) {
        int n = (w << 3) + (it2 << 2) + rgrp;
        int col = (((n >> 2) ^ g) << 2) + (n & 3);
        __align__(16) __half h[8];
        #pragma unroll
        for (int i = 0; i < 8; i++) h[i] = __float2half_rn(t[koff + i][col]);
        *reinterpret_cast<uint4*>(out + (size_t)(n0 + n) * K + k0 + koff) =
            *reinterpret_cast<uint4*>(h);
    }
}

__global__ __launch_bounds__(256) void convT3(
    const float* __restrict__ in, __half* __restrict__ out, int K, int N,
    size_t inStride, size_t outStride)
{
    convT_core(in + (size_t)blockIdx.z * inStride,
               out + (size_t)blockIdx.z * outStride,
               K, N, blockIdx.x * 64, blockIdx.y * 64, threadIdx.x);
}

// All gate weights in one launch: z in [0, 15) -> layer z/3, gate z%3.
__global__ __launch_bounds__(256) void conv_gatesT(
    const float* __restrict__ Wd, const float* __restrict__ Wf,
    const float* __restrict__ Wi)
{
    int z = blockIdx.z, l = z / 3, gI = z - l * 3;
    const float* in = (gI == 0 ? Wd : (gI == 1 ? Wf : Wi)) + (size_t)l * H_DIM * C_DIM;
    __half* out = g_WgT + ((size_t)l * 3072 + (size_t)gI * 1024) * H_DIM;
    convT_core(in, out, H_DIM, C_DIM, blockIdx.x * 64, blockIdx.y * 64, threadIdx.x);
}

// ---------------------------------------------------------------------------
// Block reduction (256 threads)
// ---------------------------------------------------------------------------
__device__ __forceinline__ float block_sum(float v) {
    __shared__ float sbuf[8];
    #pragma unroll
    for (int o = 16; o; o >>= 1) v += __shfl_xor_sync(0xffffffffu, v, o);
    if ((threadIdx.x & 31) == 0) sbuf[threadIdx.x >> 5] = v;
    __syncthreads();
    if (threadIdx.x < 32) {
        float s = (threadIdx.x < 8) ? sbuf[threadIdx.x] : 0.f;
        #pragma unroll
        for (int o = 4; o; o >>= 1) s += __shfl_xor_sync(0xffffffffu, s, o);
        if (threadIdx.x == 0) sbuf[0] = s;
    }
    __syncthreads();
    float r = sbuf[0];
    __syncthreads();
    return r;
}

// ---------------------------------------------------------------------------
// Embedding gather + LN -> fp16 x; zero ctx halves
// ---------------------------------------------------------------------------
__global__ __launch_bounds__(256) void embed_ln_kernel(
    const int* __restrict__ ids, const float* __restrict__ emb,
    const float* __restrict__ gw, const float* __restrict__ bw)
{
    int n = blockIdx.x;
    const float* row = emb + (size_t)ids[n] * E_DIM;
    float v[4]; float s = 0.f;
    #pragma unroll
    for (int i = 0; i < 4; i++) { v[i] = row[threadIdx.x + (i << 8)]; s += v[i]; }
    float mean = block_sum(s) * (1.f / E_DIM);
    float q = 0.f;
    #pragma unroll
    for (int i = 0; i < 4; i++) { float d = v[i] - mean; q += d * d; }
    float rstd = rsqrtf(block_sum(q) * (1.f / E_DIM) + LN_EPS);
    __half* out = g_xc + (size_t)n * 2048;
    float* ctx = g_ctx + (size_t)n * C_DIM;
    #pragma unroll
    for (int i = 0; i < 4; i++) {
        int j = threadIdx.x + (i << 8);
        out[j] = __float2half_rn((v[i] - mean) * rstd * gw[j] + bw[j]);
        out[1024 + j] = __float2half_rn(0.f);
        ctx[j] = 0.f;
    }
}

// ---------------------------------------------------------------------------
// Gates -> context update + LN + clip
// ---------------------------------------------------------------------------
__global__ __launch_bounds__(256) void ctx_kernel(
    const float* __restrict__ gw, const float* __restrict__ bw)
{
    int n = blockIdx.x;
    const float* g = g_gates + (size_t)n * 3072;
    float* ctx = g_ctx + (size_t)n * C_DIM;
    __half* cxh = g_xc + (size_t)n * 2048 + 1024;
    float v[4]; float s = 0.f;
    #pragma unroll
    for (int i = 0; i < 4; i++) {
        int j = threadIdx.x + (i << 8);
        float d  = tanhf(g[j]);
        float fg = 1.f / (1.f + expf(-g[1024 + j]));
        float ig = 1.f / (1.f + expf(-g[2048 + j]));
        v[i] = fg * ctx[j] + ig * d;
        s += v[i];
    }
    float mean = block_sum(s) * (1.f / C_DIM);
    float q = 0.f;
    #pragma unroll
    for (int i = 0; i < 4; i++) { float d = v[i] - mean; q += d * d; }
    float rstd = rsqrtf(block_sum(q) * (1.f / C_DIM) + LN_EPS);
    #pragma unroll
    for (int i = 0; i < 4; i++) {
        int j = threadIdx.x + (i << 8);
        float ov = (v[i] - mean) * rstd * gw[j] + bw[j];
        ov = fminf(fmaxf(ov, -10.f), 10.f);
        ctx[j] = ov;
        cxh[j] = __float2half_rn(ov);
    }
}

// all 5 layers' gate biases at once: g_bg[l][3072] = bd|bf|bi of layer l
__global__ void catbias(const float* __restrict__ bd, const float* __restrict__ bf,
                        const float* __restrict__ bi)
{
    int lin = blockIdx.x * 256 + threadIdx.x;      // < 5*3072
    if (lin >= (L_NUM - 1) * 3072) return;
    int l = lin / 3072, j = lin % 3072;
    float v;
    if (j < 1024)      v = bd[(size_t)l * C_DIM + j];
    else if (j < 2048) v = bf[(size_t)l * C_DIM + j - 1024];
    else               v = bi[(size_t)l * C_DIM + j - 2048];
    g_bg[lin] = v;
}

// ---------------------------------------------------------------------------
// Launch (serial; overlap was measured SM-bound-neutral in R9)
// ---------------------------------------------------------------------------
extern "C" void kernel_launch(void* const* d_in, const int* in_sizes, int n_in,
                              void* d_out, int out_size)
{
    (void)in_sizes; (void)n_in; (void)out_size;
    const int*   ids  = (const int*)d_in[0];
    const float* emb  = (const float*)d_in[1];
    const float* en_g = (const float*)d_in[2];
    const float* en_b = (const float*)d_in[3];
    const float* W1   = (const float*)d_in[4];
    const float* b1   = (const float*)d_in[5];
    const float* Wd   = (const float*)d_in[6];
    const float* bd   = (const float*)d_in[7];
    const float* Wf   = (const float*)d_in[8];
    const float* bf   = (const float*)d_in[9];
    const float* Wi   = (const float*)d_in[10];
    const float* bi   = (const float*)d_in[11];
    const float* lng  = (const float*)d_in[12];
    const float* lnb  = (const float*)d_in[13];
    const float* Wout = (const float*)d_in[14];
    const float* bout = (const float*)d_in[15];
    float* out = (float*)d_out;

    __half *W1T, *WgT, *WoutT, *xc, *hid;
    float *gates, *bg;
    cudaGetSymbolAddress((void**)&W1T, g_W1T);
    cudaGetSymbolAddress((void**)&WgT, g_WgT);
    cudaGetSymbolAddress((void**)&WoutT, g_WoutT);
    cudaGetSymbolAddress((void**)&xc, g_xc);
    cudaGetSymbolAddress((void**)&hid, g_hidden);
    cudaGetSymbolAddress((void**)&gates, g_gates);
    cudaGetSymbolAddress((void**)&bg, g_bg);

    cudaFuncSetAttribute(gemm_hmma, cudaFuncAttributeMaxDynamicSharedMemorySize, SMEM_GEMM);

    // ---- weight conversions (fp32 [K][N] -> fp16 [N][K]) ----
    convT3<<<dim3(H_DIM / 64, 2048 / 64, L_NUM), 256>>>(
        W1, W1T, 2048, H_DIM, (size_t)2048 * H_DIM, (size_t)H_DIM * 2048);
    conv_gatesT<<<dim3(C_DIM / 64, H_DIM / 64, 3 * (L_NUM - 1)), 256>>>(Wd, Wf, Wi);
    convT3<<<dim3(V_DIM / 64, H_DIM / 64, 1), 256>>>(
        Wout, WoutT, H_DIM, V_DIM, 0, 0);

    catbias<<<60, 256>>>(bd, bf, bi);
    embed_ln_kernel<<<N_TOK, 256>>>(ids, emb, en_g, en_b);

    dim3 gH(N_TOK / 128, H_DIM / 128);   // (32, 32)
    dim3 gG(N_TOK / 128, 3072 / 128);    // (32, 24)
    dim3 gV(N_TOK / 128, V_DIM / 128);   // (32, 250)

    for (int l = 0; l < L_NUM; l++) {
        int Keff = (l == 0) ? E_DIM : 2048;
        gemm_hmma<<<gH, 128, SMEM_GEMM>>>(
            xc, 2048, W1T + (size_t)l * H_DIM * 2048, 2048,
            b1 + (size_t)l * H_DIM, hid, H_DIM, Keff, 1);

        if (l < L_NUM - 1) {
            gemm_hmma<<<gG, 128, SMEM_GEMM>>>(
                hid, H_DIM, WgT + (size_t)l * 3072 * H_DIM, H_DIM,
                bg + (size_t)l * 3072, gates, 3072, H_DIM, 0);
            ctx_kernel<<<N_TOK, 256>>>(lng + (size_t)l * C_DIM, lnb + (size_t)l * C_DIM);
        }
    }

    gemm_hmma<<<gV, 128, SMEM_GEMM>>>(hid, H_DIM, WoutT, H_DIM, bout, out, V_DIM, H_DIM, 0);
}

// round 13
// speedup vs baseline: 1.0293x; 1.0012x over previous
#include <cuda_runtime.h>
#include <cuda_fp16.h>
#include <cstdint>
#include <math.h>

#define E_DIM 1024
#define C_DIM 1024
#define H_DIM 4096
#define V_DIM 32000
#define L_NUM 6
#define N_TOK 4096
#define LN_EPS 1e-5f

// ---------------------------------------------------------------------------
// Static device scratch (no allocation allowed). Weights pre-transposed [N][K].
// ---------------------------------------------------------------------------
__device__ __half g_W1T[(size_t)L_NUM * H_DIM * 2048];     // [L][4096][2048]
__device__ __half g_WgT[(size_t)L_NUM * 3072 * H_DIM];     // [L][3072][4096] (d|f|i)
__device__ __half g_WoutT[(size_t)V_DIM * H_DIM];          // [32000][4096]
__device__ __half g_xc[(size_t)N_TOK * 2048];              // [x | ctx] fp16 GEMM A
__device__ __half g_hidden[(size_t)N_TOK * H_DIM];         // fp16 GEMM A
__device__ float  g_ctx[(size_t)N_TOK * C_DIM];            // fp32 recurrence
__device__ float  g_gates[(size_t)N_TOK * 3072];           // gate pre-activations
__device__ float  g_bg[(size_t)(L_NUM - 1) * 3072];        // concat gate biases

__device__ __forceinline__ uint32_t smem_u32(const void* p) {
    uint32_t a;
    asm("{ .reg .u64 t; cvta.to.shared.u64 t, %1; cvt.u32.u64 %0, t; }" : "=r"(a) : "l"(p));
    return a;
}

// ---------------------------------------------------------------------------
// GEMM: C[M,N] = act(A[M,K] @ B^T + bias), A row-major fp16 (lda),
// B fp16 [N][K] K-major (ldb). CTA tile 128x128x64, 3-stage cp.async,
// ldmatrix x4 + mma.sync m16n8k16 fp32 accum.
// 128 threads = 4 warps in 2(M) x 2(N), warp tile 64x64. 2 CTAs/SM (96KB).
// ---------------------------------------------------------------------------
#define BK 64
#define STAGE_BYTES 32768u     // A 16KB + B 16KB
#define SMEM_GEMM   98304      // 3 stages

__device__ __forceinline__ void cp16(uint32_t d, const void* g) {
    asm volatile("cp.async.cg.shared.global [%0], [%1], 16;\n" :: "r"(d), "l"(g) : "memory");
}

__device__ __forceinline__ void load_stage(
    uint32_t sb, int s, const __half* __restrict__ Ab, int lda,
    const __half* __restrict__ Bb, int ldb, int kt, int tid)
{
    uint32_t base = sb + (uint32_t)s * STAGE_BYTES;
    int k0 = kt * BK;
    #pragma unroll
    for (int j = 0; j < 8; j++) {           // A: 128 rows (M) x 8 chunks
        int i = tid + (j << 7);
        int r = i >> 3, c = i & 7;
        cp16(base + (r << 7) + ((uint32_t)(c ^ (r & 7)) << 4),
             Ab + (size_t)r * lda + k0 + (c << 3));
    }
    #pragma unroll
    for (int j = 0; j < 8; j++) {           // B: 128 rows (N) x 8 chunks
        int i = tid + (j << 7);
        int r = i >> 3, c = i & 7;
        cp16(base + 16384u + (r << 7) + ((uint32_t)(c ^ (r & 7)) << 4),
             Bb + (size_t)r * ldb + k0 + (c << 3));
    }
    asm volatile("cp.async.commit_group;\n" ::: "memory");
}

__global__ __launch_bounds__(128, 2) void gemm_hmma(
    const __half* __restrict__ A, int lda,
    const __half* __restrict__ B, int ldb,
    const float* __restrict__ bias,
    void* __restrict__ Cout, int ldc,
    int K, int mode)   // mode 0: fp32 out; 1: relu -> fp16 out
{
    extern __shared__ __align__(128) char smem[];
    uint32_t sb = smem_u32(smem);
    const int tid = threadIdx.x, lane = tid & 31, warp = tid >> 5;
    const int mW = (warp >> 1) * 64;       // 2 warps in M
    const int nW = (warp & 1) * 64;        // 2 warps in N

    const size_t m0 = (size_t)blockIdx.x * 128;
    const size_t n0 = (size_t)blockIdx.y * 128;
    const __half* Ab = A + m0 * (size_t)lda;
    const __half* Bb = B + n0 * (size_t)ldb;

    const int KT = K / BK;

    load_stage(sb, 0, Ab, lda, Bb, ldb, 0, tid);
    if (KT > 1) load_stage(sb, 1, Ab, lda, Bb, ldb, 1, tid);

    float acc[4][8][4];
    #pragma unroll
    for (int i = 0; i < 4; i++)
        #pragma unroll
        for (int j = 0; j < 8; j++) {
            acc[i][j][0] = 0.f; acc[i][j][1] = 0.f;
            acc[i][j][2] = 0.f; acc[i][j][3] = 0.f;
        }

    // ldmatrix lane addressing
    const int a_row = mW + (lane & 15);            // + mt*16
    const int a_chk = lane >> 4;                   // + ks*2
    const int grp   = lane >> 3;                   // B x4 lane group
    const int b_row_off = (lane & 7) + ((grp >> 1) << 3);   // 0..15
    const int b_chk = grp & 1;                     // k-half within 16

    for (int kt = 0; kt < KT; kt++) {
        if (kt + 1 < KT) asm volatile("cp.async.wait_group 1;\n" ::: "memory");
        else             asm volatile("cp.async.wait_group 0;\n" ::: "memory");
        __syncthreads();   // single barrier per iteration (orders buffer reuse too)

        if (kt + 2 < KT)
            load_stage(sb, (kt + 2) % 3, Ab, lda, Bb, ldb, kt + 2, tid);

        uint32_t abase = sb + (uint32_t)(kt % 3) * STAGE_BYTES;
        uint32_t bbase = abase + 16384u;

        #pragma unroll
        for (int ks = 0; ks < 4; ks++) {
            uint32_t af[4][4], bf[8][2];
            #pragma unroll
            for (int mt = 0; mt < 4; mt++) {
                int r = a_row + mt * 16;
                int ch = (ks * 2 + a_chk) ^ (r & 7);
                uint32_t ad = abase + (r << 7) + (ch << 4);
                asm volatile("ldmatrix.sync.aligned.m8n8.x4.shared.b16 {%0,%1,%2,%3}, [%4];"
                    : "=r"(af[mt][0]), "=r"(af[mt][1]), "=r"(af[mt][2]), "=r"(af[mt][3])
                    : "r"(ad));
            }
            #pragma unroll
            for (int ntp = 0; ntp < 4; ntp++) {    // pair of 8-col n-groups
                int r = nW + ntp * 16 + b_row_off;
                int ch = (ks * 2 + b_chk) ^ (r & 7);
                uint32_t bd = bbase + (r << 7) + (ch << 4);
                asm volatile("ldmatrix.sync.aligned.m8n8.x4.shared.b16 {%0,%1,%2,%3}, [%4];"
                    : "=r"(bf[2*ntp][0]), "=r"(bf[2*ntp][1]),
                      "=r"(bf[2*ntp+1][0]), "=r"(bf[2*ntp+1][1])
                    : "r"(bd));
            }
            #pragma unroll
            for (int mt = 0; mt < 4; mt++)
                #pragma unroll
                for (int nt = 0; nt < 8; nt++)
                    asm volatile(
                        "mma.sync.aligned.m16n8k16.row.col.f32.f16.f16.f32 "
                        "{%0,%1,%2,%3}, {%4,%5,%6,%7}, {%8,%9}, {%0,%1,%2,%3};"
                        : "+f"(acc[mt][nt][0]), "+f"(acc[mt][nt][1]),
                          "+f"(acc[mt][nt][2]), "+f"(acc[mt][nt][3])
                        : "r"(af[mt][0]), "r"(af[mt][1]), "r"(af[mt][2]), "r"(af[mt][3]),
                          "r"(bf[nt][0]), "r"(bf[nt][1]));
        }
    }

    // Epilogue
    const int er = lane >> 2, ec = (lane & 3) * 2;
    #pragma unroll
    for (int mt = 0; mt < 4; mt++) {
        size_t mA = m0 + mW + mt * 16 + er;
        size_t mB = mA + 8;
        #pragma unroll
        for (int nt = 0; nt < 8; nt++) {
            size_t n = n0 + nW + nt * 8 + ec;
            float b0 = bias[n], b1 = bias[n + 1];
            float v0 = acc[mt][nt][0] + b0;
            float v1 = acc[mt][nt][1] + b1;
            float v2 = acc[mt][nt][2] + b0;
            float v3 = acc[mt][nt][3] + b1;
            if (mode == 0) {
                float* o = (float*)Cout;
                *reinterpret_cast<float2*>(o + mA * (size_t)ldc + n) = make_float2(v0, v1);
                *reinterpret_cast<float2*>(o + mB * (size_t)ldc + n) = make_float2(v2, v3);
            } else {
                __half* o = (__half*)Cout;
                v0 = fmaxf(v0, 0.f); v1 = fmaxf(v1, 0.f);
                v2 = fmaxf(v2, 0.f); v3 = fmaxf(v3, 0.f);
                *reinterpret_cast<__half2*>(o + mA * (size_t)ldc + n) = __floats2half2_rn(v0, v1);
                *reinterpret_cast<__half2*>(o + mB * (size_t)ldc + n) = __floats2half2_rn(v2, v3);
            }
        }
    }
}

// ---------------------------------------------------------------------------
// Write-coalesced transposing fp32->fp16 convert: out[n][k] = in[k][n].
// 64x64 tile, 256 threads, XOR-swizzled smem t[64][64] (no padding):
// element (k,n) lives at col 4*((n>>2)^((k>>3)&7)) + (n&3).
//  - Phase-1 float4 stores: rows are 256B -> always 16B aligned.
//  - Phase-2 reads conflict-free; global stores 4 n-rows x 128B contiguous.
// ---------------------------------------------------------------------------
__device__ __forceinline__ void convT_core(
    const float* __restrict__ in, __half* __restrict__ out, int K, int N,
    int n0, int k0, int tid)
{
    __shared__ float t[64][64];
    const int lr = tid >> 4, cg = tid & 15;        // k-row base, n col-group
    #pragma unroll
    for (int it = 0; it < 4; it++) {
        int k = lr + it * 16;
        float4 v = *reinterpret_cast<const float4*>(
            in + (size_t)(k0 + k) * N + n0 + (cg << 2));
        int cgs = cg ^ ((k >> 3) & 7);
        *reinterpret_cast<float4*>(&t[k][cgs << 2]) = v;
    }
    __syncthreads();
    const int w = tid >> 5, lane = tid & 31;
    const int g = lane & 7, rgrp = lane >> 3;
    const int koff = g << 3;
    #pragma unroll
    for (int it2 = 0; it2 < 2; it2++) {
        int n = (w << 3) + (it2 << 2) + rgrp;
        int col = (((n >> 2) ^ g) << 2) + (n & 3);
        __align__(16) __half h[8];
        #pragma unroll
        for (int i = 0; i < 8; i++) h[i] = __float2half_rn(t[koff + i][col]);
        *reinterpret_cast<uint4*>(out + (size_t)(n0 + n) * K + k0 + koff) =
            *reinterpret_cast<uint4*>(h);
    }
}

// skipL0HighK: layer 0 (z==0) only reads k<1024 of W1T -> skip those tiles.
__global__ __launch_bounds__(256) void convT3(
    const float* __restrict__ in, __half* __restrict__ out, int K, int N,
    size_t inStride, size_t outStride, int skipL0HighK)
{
    if (skipL0HighK && blockIdx.z == 0 && (int)(blockIdx.y * 64) >= 1024) return;
    convT_core(in + (size_t)blockIdx.z * inStride,
               out + (size_t)blockIdx.z * outStride,
               K, N, blockIdx.x * 64, blockIdx.y * 64, threadIdx.x);
}

// All gate weights in one launch: z in [0, 15) -> layer z/3, gate z%3.
__global__ __launch_bounds__(256) void conv_gatesT(
    const float* __restrict__ Wd, const float* __restrict__ Wf,
    const float* __restrict__ Wi)
{
    int z = blockIdx.z, l = z / 3, gI = z - l * 3;
    const float* in = (gI == 0 ? Wd : (gI == 1 ? Wf : Wi)) + (size_t)l * H_DIM * C_DIM;
    __half* out = g_WgT + ((size_t)l * 3072 + (size_t)gI * 1024) * H_DIM;
    convT_core(in, out, H_DIM, C_DIM, blockIdx.x * 64, blockIdx.y * 64, threadIdx.x);
}

// ---------------------------------------------------------------------------
// Block reduction (256 threads)
// ---------------------------------------------------------------------------
__device__ __forceinline__ float block_sum(float v) {
    __shared__ float sbuf[8];
    #pragma unroll
    for (int o = 16; o; o >>= 1) v += __shfl_xor_sync(0xffffffffu, v, o);
    if ((threadIdx.x & 31) == 0) sbuf[threadIdx.x >> 5] = v;
    __syncthreads();
    if (threadIdx.x < 32) {
        float s = (threadIdx.x < 8) ? sbuf[threadIdx.x] : 0.f;
        #pragma unroll
        for (int o = 4; o; o >>= 1) s += __shfl_xor_sync(0xffffffffu, s, o);
        if (threadIdx.x == 0) sbuf[0] = s;
    }
    __syncthreads();
    float r = sbuf[0];
    __syncthreads();
    return r;
}

// ---------------------------------------------------------------------------
// Embedding gather + LN -> fp16 x; zero ctx halves
// ---------------------------------------------------------------------------
__global__ __launch_bounds__(256) void embed_ln_kernel(
    const int* __restrict__ ids, const float* __restrict__ emb,
    const float* __restrict__ gw, const float* __restrict__ bw)
{
    int n = blockIdx.x;
    const float* row = emb + (size_t)ids[n] * E_DIM;
    float v[4]; float s = 0.f;
    #pragma unroll
    for (int i = 0; i < 4; i++) { v[i] = row[threadIdx.x + (i << 8)]; s += v[i]; }
    float mean = block_sum(s) * (1.f / E_DIM);
    float q = 0.f;
    #pragma unroll
    for (int i = 0; i < 4; i++) { float d = v[i] - mean; q += d * d; }
    float rstd = rsqrtf(block_sum(q) * (1.f / E_DIM) + LN_EPS);
    __half* out = g_xc + (size_t)n * 2048;
    float* ctx = g_ctx + (size_t)n * C_DIM;
    #pragma unroll
    for (int i = 0; i < 4; i++) {
        int j = threadIdx.x + (i << 8);
        out[j] = __float2half_rn((v[i] - mean) * rstd * gw[j] + bw[j]);
        out[1024 + j] = __float2half_rn(0.f);
        ctx[j] = 0.f;
    }
}

// ---------------------------------------------------------------------------
// Gates -> context update + LN + clip
// ---------------------------------------------------------------------------
__global__ __launch_bounds__(256) void ctx_kernel(
    const float* __restrict__ gw, const float* __restrict__ bw)
{
    int n = blockIdx.x;
    const float* g = g_gates + (size_t)n * 3072;
    float* ctx = g_ctx + (size_t)n * C_DIM;
    __half* cxh = g_xc + (size_t)n * 2048 + 1024;
    float v[4]; float s = 0.f;
    #pragma unroll
    for (int i = 0; i < 4; i++) {
        int j = threadIdx.x + (i << 8);
        float d  = tanhf(g[j]);
        float fg = 1.f / (1.f + expf(-g[1024 + j]));
        float ig = 1.f / (1.f + expf(-g[2048 + j]));
        v[i] = fg * ctx[j] + ig * d;
        s += v[i];
    }
    float mean = block_sum(s) * (1.f / C_DIM);
    float q = 0.f;
    #pragma unroll
    for (int i = 0; i < 4; i++) { float d = v[i] - mean; q += d * d; }
    float rstd = rsqrtf(block_sum(q) * (1.f / C_DIM) + LN_EPS);
    #pragma unroll
    for (int i = 0; i < 4; i++) {
        int j = threadIdx.x + (i << 8);
        float ov = (v[i] - mean) * rstd * gw[j] + bw[j];
        ov = fminf(fmaxf(ov, -10.f), 10.f);
        ctx[j] = ov;
        cxh[j] = __float2half_rn(ov);
    }
}

// all 5 layers' gate biases at once: g_bg[l][3072] = bd|bf|bi of layer l
__global__ void catbias(const float* __restrict__ bd, const float* __restrict__ bf,
                        const float* __restrict__ bi)
{
    int lin = blockIdx.x * 256 + threadIdx.x;      // < 5*3072
    if (lin >= (L_NUM - 1) * 3072) return;
    int l = lin / 3072, j = lin % 3072;
    float v;
    if (j < 1024)      v = bd[(size_t)l * C_DIM + j];
    else if (j < 2048) v = bf[(size_t)l * C_DIM + j - 1024];
    else               v = bi[(size_t)l * C_DIM + j - 2048];
    g_bg[lin] = v;
}

// ---------------------------------------------------------------------------
// Launch. Order puts the 5 prologue kernels first so ncu (-s 5) profiles
// the first W1 GEMM.
// ---------------------------------------------------------------------------
extern "C" void kernel_launch(void* const* d_in, const int* in_sizes, int n_in,
                              void* d_out, int out_size)
{
    (void)in_sizes; (void)n_in; (void)out_size;
    const int*   ids  = (const int*)d_in[0];
    const float* emb  = (const float*)d_in[1];
    const float* en_g = (const float*)d_in[2];
    const float* en_b = (const float*)d_in[3];
    const float* W1   = (const float*)d_in[4];
    const float* b1   = (const float*)d_in[5];
    const float* Wd   = (const float*)d_in[6];
    const float* bd   = (const float*)d_in[7];
    const float* Wf   = (const float*)d_in[8];
    const float* bf   = (const float*)d_in[9];
    const float* Wi   = (const float*)d_in[10];
    const float* bi   = (const float*)d_in[11];
    const float* lng  = (const float*)d_in[12];
    const float* lnb  = (const float*)d_in[13];
    const float* Wout = (const float*)d_in[14];
    const float* bout = (const float*)d_in[15];
    float* out = (float*)d_out;

    __half *W1T, *WgT, *WoutT, *xc, *hid;
    float *gates, *bg;
    cudaGetSymbolAddress((void**)&W1T, g_W1T);
    cudaGetSymbolAddress((void**)&WgT, g_WgT);
    cudaGetSymbolAddress((void**)&WoutT, g_WoutT);
    cudaGetSymbolAddress((void**)&xc, g_xc);
    cudaGetSymbolAddress((void**)&hid, g_hidden);
    cudaGetSymbolAddress((void**)&gates, g_gates);
    cudaGetSymbolAddress((void**)&bg, g_bg);

    cudaFuncSetAttribute(gemm_hmma, cudaFuncAttributeMaxDynamicSharedMemorySize, SMEM_GEMM);

    // ---- prologue: biases + embed first (launch indices 0,1) ----
    catbias<<<60, 256>>>(bd, bf, bi);
    embed_ln_kernel<<<N_TOK, 256>>>(ids, emb, en_g, en_b);

    // ---- weight conversions (fp32 [K][N] -> fp16 [N][K]) : indices 2,3,4 ----
    convT3<<<dim3(H_DIM / 64, 2048 / 64, L_NUM), 256>>>(
        W1, W1T, 2048, H_DIM, (size_t)2048 * H_DIM, (size_t)H_DIM * 2048, 1);
    conv_gatesT<<<dim3(C_DIM / 64, H_DIM / 64, 3 * (L_NUM - 1)), 256>>>(Wd, Wf, Wi);
    convT3<<<dim3(V_DIM / 64, H_DIM / 64, 1), 256>>>(
        Wout, WoutT, H_DIM, V_DIM, 0, 0, 0);

    dim3 gH(N_TOK / 128, H_DIM / 128);   // (32, 32)
    dim3 gG(N_TOK / 128, 3072 / 128);    // (32, 24)
    dim3 gV(N_TOK / 128, V_DIM / 128);   // (32, 250)

    for (int l = 0; l < L_NUM; l++) {
        int Keff = (l == 0) ? E_DIM : 2048;
        gemm_hmma<<<gH, 128, SMEM_GEMM>>>(
            xc, 2048, W1T + (size_t)l * H_DIM * 2048, 2048,
            b1 + (size_t)l * H_DIM, hid, H_DIM, Keff, 1);

        if (l < L_NUM - 1) {
            gemm_hmma<<<gG, 128, SMEM_GEMM>>>(
                hid, H_DIM, WgT + (size_t)l * 3072 * H_DIM, H_DIM,
                bg + (size_t)l * 3072, gates, 3072, H_DIM, 0);
            ctx_kernel<<<N_TOK, 256>>>(lng + (size_t)l * C_DIM, lnb + (size_t)l * C_DIM);
        }
    }

    gemm_hmma<<<gV, 128, SMEM_GEMM>>>(hid, H_DIM, WoutT, H_DIM, bout, out, V_DIM, H_DIM, 0);
}

// round 14
// speedup vs baseline: 1.0299x; 1.0006x over previous
#include <cuda_runtime.h>
#include <cuda_fp16.h>
#include <cstdint>
#include <math.h>

#define E_DIM 1024
#define C_DIM 1024
#define H_DIM 4096
#define V_DIM 32000
#define L_NUM 6
#define N_TOK 4096
#define LN_EPS 1e-5f

// ---------------------------------------------------------------------------
// Static device scratch (no allocation allowed). Weights pre-transposed [N][K].
// ---------------------------------------------------------------------------
__device__ __half g_W1T[(size_t)L_NUM * H_DIM * 2048];     // [L][4096][2048]
__device__ __half g_WgT[(size_t)L_NUM * 3072 * H_DIM];     // [L][3072][4096] (d|f|i)
__device__ __half g_WoutT[(size_t)V_DIM * H_DIM];          // [32000][4096]
__device__ __half g_xc[(size_t)N_TOK * 2048];              // [x | ctx] fp16 GEMM A
__device__ __half g_hidden[(size_t)N_TOK * H_DIM];         // fp16 GEMM A
__device__ float  g_ctx[(size_t)N_TOK * C_DIM];            // fp32 recurrence
__device__ float  g_gates[(size_t)N_TOK * 3072];           // gate pre-activations
__device__ float  g_bg[(size_t)(L_NUM - 1) * 3072];        // concat gate biases

__device__ __forceinline__ uint32_t smem_u32(const void* p) {
    uint32_t a;
    asm("{ .reg .u64 t; cvta.to.shared.u64 t, %1; cvt.u32.u64 %0, t; }" : "=r"(a) : "l"(p));
    return a;
}

// ---------------------------------------------------------------------------
// GEMM: C[M,N] = act(A[M,K] @ B^T + bias), A row-major fp16 (lda),
// B fp16 [N][K] K-major (ldb). CTA tile 128x128x64, 3-stage cp.async,
// ldmatrix x4 + mma.sync m16n8k16 fp32 accum.
// 128 threads = 4 warps in 2(M) x 2(N), warp tile 64x64. 2 CTAs/SM (96KB).
// ---------------------------------------------------------------------------
#define BK 64
#define STAGE_BYTES 32768u     // A 16KB + B 16KB
#define SMEM_GEMM   98304      // 3 stages

__device__ __forceinline__ void cp16(uint32_t d, const void* g) {
    asm volatile("cp.async.cg.shared.global [%0], [%1], 16;\n" :: "r"(d), "l"(g) : "memory");
}

__device__ __forceinline__ void load_stage(
    uint32_t sb, int s, const __half* __restrict__ Ab, int lda,
    const __half* __restrict__ Bb, int ldb, int kt, int tid)
{
    uint32_t base = sb + (uint32_t)s * STAGE_BYTES;
    int k0 = kt * BK;
    #pragma unroll
    for (int j = 0; j < 8; j++) {           // A: 128 rows (M) x 8 chunks
        int i = tid + (j << 7);
        int r = i >> 3, c = i & 7;
        cp16(base + (r << 7) + ((uint32_t)(c ^ (r & 7)) << 4),
             Ab + (size_t)r * lda + k0 + (c << 3));
    }
    #pragma unroll
    for (int j = 0; j < 8; j++) {           // B: 128 rows (N) x 8 chunks
        int i = tid + (j << 7);
        int r = i >> 3, c = i & 7;
        cp16(base + 16384u + (r << 7) + ((uint32_t)(c ^ (r & 7)) << 4),
             Bb + (size_t)r * ldb + k0 + (c << 3));
    }
    asm volatile("cp.async.commit_group;\n" ::: "memory");
}

__global__ __launch_bounds__(128, 2) void gemm_hmma(
    const __half* __restrict__ A, int lda,
    const __half* __restrict__ B, int ldb,
    const float* __restrict__ bias,
    void* __restrict__ Cout, int ldc,
    int K, int mode)   // mode 0: fp32 out; 1: relu -> fp16 out
{
    extern __shared__ __align__(128) char smem[];
    uint32_t sb = smem_u32(smem);
    const int tid = threadIdx.x, lane = tid & 31, warp = tid >> 5;
    const int mW = (warp >> 1) * 64;       // 2 warps in M
    const int nW = (warp & 1) * 64;        // 2 warps in N

    const size_t m0 = (size_t)blockIdx.x * 128;
    const size_t n0 = (size_t)blockIdx.y * 128;
    const __half* Ab = A + m0 * (size_t)lda;
    const __half* Bb = B + n0 * (size_t)ldb;

    const int KT = K / BK;

    load_stage(sb, 0, Ab, lda, Bb, ldb, 0, tid);
    if (KT > 1) load_stage(sb, 1, Ab, lda, Bb, ldb, 1, tid);

    float acc[4][8][4];
    #pragma unroll
    for (int i = 0; i < 4; i++)
        #pragma unroll
        for (int j = 0; j < 8; j++) {
            acc[i][j][0] = 0.f; acc[i][j][1] = 0.f;
            acc[i][j][2] = 0.f; acc[i][j][3] = 0.f;
        }

    // ldmatrix lane addressing
    const int a_row = mW + (lane & 15);            // + mt*16
    const int a_chk = lane >> 4;                   // + ks*2
    const int grp   = lane >> 3;                   // B x4 lane group
    const int b_row_off = (lane & 7) + ((grp >> 1) << 3);   // 0..15
    const int b_chk = grp & 1;                     // k-half within 16

    for (int kt = 0; kt < KT; kt++) {
        if (kt + 1 < KT) asm volatile("cp.async.wait_group 1;\n" ::: "memory");
        else             asm volatile("cp.async.wait_group 0;\n" ::: "memory");
        __syncthreads();   // single barrier per iteration (orders buffer reuse too)

        if (kt + 2 < KT)
            load_stage(sb, (kt + 2) % 3, Ab, lda, Bb, ldb, kt + 2, tid);

        uint32_t abase = sb + (uint32_t)(kt % 3) * STAGE_BYTES;
        uint32_t bbase = abase + 16384u;

        #pragma unroll
        for (int ks = 0; ks < 4; ks++) {
            uint32_t af[4][4], bf[8][2];
            #pragma unroll
            for (int mt = 0; mt < 4; mt++) {
                int r = a_row + mt * 16;
                int ch = (ks * 2 + a_chk) ^ (r & 7);
                uint32_t ad = abase + (r << 7) + (ch << 4);
                asm volatile("ldmatrix.sync.aligned.m8n8.x4.shared.b16 {%0,%1,%2,%3}, [%4];"
                    : "=r"(af[mt][0]), "=r"(af[mt][1]), "=r"(af[mt][2]), "=r"(af[mt][3])
                    : "r"(ad));
            }
            #pragma unroll
            for (int ntp = 0; ntp < 4; ntp++) {    // pair of 8-col n-groups
                int r = nW + ntp * 16 + b_row_off;
                int ch = (ks * 2 + b_chk) ^ (r & 7);
                uint32_t bd = bbase + (r << 7) + (ch << 4);
                asm volatile("ldmatrix.sync.aligned.m8n8.x4.shared.b16 {%0,%1,%2,%3}, [%4];"
                    : "=r"(bf[2*ntp][0]), "=r"(bf[2*ntp][1]),
                      "=r"(bf[2*ntp+1][0]), "=r"(bf[2*ntp+1][1])
                    : "r"(bd));
            }
            #pragma unroll
            for (int mt = 0; mt < 4; mt++)
                #pragma unroll
                for (int nt = 0; nt < 8; nt++)
                    asm volatile(
                        "mma.sync.aligned.m16n8k16.row.col.f32.f16.f16.f32 "
                        "{%0,%1,%2,%3}, {%4,%5,%6,%7}, {%8,%9}, {%0,%1,%2,%3};"
                        : "+f"(acc[mt][nt][0]), "+f"(acc[mt][nt][1]),
                          "+f"(acc[mt][nt][2]), "+f"(acc[mt][nt][3])
                        : "r"(af[mt][0]), "r"(af[mt][1]), "r"(af[mt][2]), "r"(af[mt][3]),
                          "r"(bf[nt][0]), "r"(bf[nt][1]));
        }
    }

    // Epilogue
    const int er = lane >> 2, ec = (lane & 3) * 2;
    #pragma unroll
    for (int mt = 0; mt < 4; mt++) {
        size_t mA = m0 + mW + mt * 16 + er;
        size_t mB = mA + 8;
        #pragma unroll
        for (int nt = 0; nt < 8; nt++) {
            size_t n = n0 + nW + nt * 8 + ec;
            float b0 = bias[n], b1 = bias[n + 1];
            float v0 = acc[mt][nt][0] + b0;
            float v1 = acc[mt][nt][1] + b1;
            float v2 = acc[mt][nt][2] + b0;
            float v3 = acc[mt][nt][3] + b1;
            if (mode == 0) {
                float* o = (float*)Cout;
                *reinterpret_cast<float2*>(o + mA * (size_t)ldc + n) = make_float2(v0, v1);
                *reinterpret_cast<float2*>(o + mB * (size_t)ldc + n) = make_float2(v2, v3);
            } else {
                __half* o = (__half*)Cout;
                v0 = fmaxf(v0, 0.f); v1 = fmaxf(v1, 0.f);
                v2 = fmaxf(v2, 0.f); v3 = fmaxf(v3, 0.f);
                *reinterpret_cast<__half2*>(o + mA * (size_t)ldc + n) = __floats2half2_rn(v0, v1);
                *reinterpret_cast<__half2*>(o + mB * (size_t)ldc + n) = __floats2half2_rn(v2, v3);
            }
        }
    }
}

// ---------------------------------------------------------------------------
// Write-coalesced transposing fp32->fp16 convert: out[n][k] = in[k][n].
// 64x64 tile, 256 threads, XOR-swizzled smem t[64][64] (no padding).
// Measured 6.4 TB/s / DRAM=81% (R13) — near HBM roofline.
// ---------------------------------------------------------------------------
__device__ __forceinline__ void convT_core(
    const float* __restrict__ in, __half* __restrict__ out, int K, int N,
    int n0, int k0, int tid)
{
    __shared__ float t[64][64];
    const int lr = tid >> 4, cg = tid & 15;        // k-row base, n col-group
    #pragma unroll
    for (int it = 0; it < 4; it++) {
        int k = lr + it * 16;
        float4 v = *reinterpret_cast<const float4*>(
            in + (size_t)(k0 + k) * N + n0 + (cg << 2));
        int cgs = cg ^ ((k >> 3) & 7);
        *reinterpret_cast<float4*>(&t[k][cgs << 2]) = v;
    }
    __syncthreads();
    const int w = tid >> 5, lane = tid & 31;
    const int g = lane & 7, rgrp = lane >> 3;
    const int koff = g << 3;
    #pragma unroll
    for (int it2 = 0; it2 < 2; it2++) {
        int n = (w << 3) + (it2 << 2) + rgrp;
        int col = (((n >> 2) ^ g) << 2) + (n & 3);
        __align__(16) __half h[8];
        #pragma unroll
        for (int i = 0; i < 8; i++) h[i] = __float2half_rn(t[koff + i][col]);
        *reinterpret_cast<uint4*>(out + (size_t)(n0 + n) * K + k0 + koff) =
            *reinterpret_cast<uint4*>(h);
    }
}

// skipL0HighK: layer 0 (z==0) only reads k<1024 of W1T -> skip those tiles.
__global__ __launch_bounds__(256) void convT3(
    const float* __restrict__ in, __half* __restrict__ out, int K, int N,
    size_t inStride, size_t outStride, int skipL0HighK)
{
    if (skipL0HighK && blockIdx.z == 0 && (int)(blockIdx.y * 64) >= 1024) return;
    convT_core(in + (size_t)blockIdx.z * inStride,
               out + (size_t)blockIdx.z * outStride,
               K, N, blockIdx.x * 64, blockIdx.y * 64, threadIdx.x);
}

// All gate weights in one launch: z in [0, 15) -> layer z/3, gate z%3.
__global__ __launch_bounds__(256) void conv_gatesT(
    const float* __restrict__ Wd, const float* __restrict__ Wf,
    const float* __restrict__ Wi)
{
    int z = blockIdx.z, l = z / 3, gI = z - l * 3;
    const float* in = (gI == 0 ? Wd : (gI == 1 ? Wf : Wi)) + (size_t)l * H_DIM * C_DIM;
    __half* out = g_WgT + ((size_t)l * 3072 + (size_t)gI * 1024) * H_DIM;
    convT_core(in, out, H_DIM, C_DIM, blockIdx.x * 64, blockIdx.y * 64, threadIdx.x);
}

// ---------------------------------------------------------------------------
// Block reduction (256 threads)
// ---------------------------------------------------------------------------
__device__ __forceinline__ float block_sum(float v) {
    __shared__ float sbuf[8];
    #pragma unroll
    for (int o = 16; o; o >>= 1) v += __shfl_xor_sync(0xffffffffu, v, o);
    if ((threadIdx.x & 31) == 0) sbuf[threadIdx.x >> 5] = v;
    __syncthreads();
    if (threadIdx.x < 32) {
        float s = (threadIdx.x < 8) ? sbuf[threadIdx.x] : 0.f;
        #pragma unroll
        for (int o = 4; o; o >>= 1) s += __shfl_xor_sync(0xffffffffu, s, o);
        if (threadIdx.x == 0) sbuf[0] = s;
    }
    __syncthreads();
    float r = sbuf[0];
    __syncthreads();
    return r;
}

// ---------------------------------------------------------------------------
// Embedding gather + LN -> fp16 x; zero ctx halves
// ---------------------------------------------------------------------------
__global__ __launch_bounds__(256) void embed_ln_kernel(
    const int* __restrict__ ids, const float* __restrict__ emb,
    const float* __restrict__ gw, const float* __restrict__ bw)
{
    int n = blockIdx.x;
    const float* row = emb + (size_t)ids[n] * E_DIM;
    float v[4]; float s = 0.f;
    #pragma unroll
    for (int i = 0; i < 4; i++) { v[i] = row[threadIdx.x + (i << 8)]; s += v[i]; }
    float mean = block_sum(s) * (1.f / E_DIM);
    float q = 0.f;
    #pragma unroll
    for (int i = 0; i < 4; i++) { float d = v[i] - mean; q += d * d; }
    float rstd = rsqrtf(block_sum(q) * (1.f / E_DIM) + LN_EPS);
    __half* out = g_xc + (size_t)n * 2048;
    float* ctx = g_ctx + (size_t)n * C_DIM;
    #pragma unroll
    for (int i = 0; i < 4; i++) {
        int j = threadIdx.x + (i << 8);
        out[j] = __float2half_rn((v[i] - mean) * rstd * gw[j] + bw[j]);
        out[1024 + j] = __float2half_rn(0.f);
        ctx[j] = 0.f;
    }
}

// ---------------------------------------------------------------------------
// Gates -> context update + LN + clip
// ---------------------------------------------------------------------------
__global__ __launch_bounds__(256) void ctx_kernel(
    const float* __restrict__ gw, const float* __restrict__ bw)
{
    int n = blockIdx.x;
    const float* g = g_gates + (size_t)n * 3072;
    float* ctx = g_ctx + (size_t)n * C_DIM;
    __half* cxh = g_xc + (size_t)n * 2048 + 1024;
    float v[4]; float s = 0.f;
    #pragma unroll
    for (int i = 0; i < 4; i++) {
        int j = threadIdx.x + (i << 8);
        float d  = tanhf(g[j]);
        float fg = 1.f / (1.f + expf(-g[1024 + j]));
        float ig = 1.f / (1.f + expf(-g[2048 + j]));
        v[i] = fg * ctx[j] + ig * d;
        s += v[i];
    }
    float mean = block_sum(s) * (1.f / C_DIM);
    float q = 0.f;
    #pragma unroll
    for (int i = 0; i < 4; i++) { float d = v[i] - mean; q += d * d; }
    float rstd = rsqrtf(block_sum(q) * (1.f / C_DIM) + LN_EPS);
    #pragma unroll
    for (int i = 0; i < 4; i++) {
        int j = threadIdx.x + (i << 8);
        float ov = (v[i] - mean) * rstd * gw[j] + bw[j];
        ov = fminf(fmaxf(ov, -10.f), 10.f);
        ctx[j] = ov;
        cxh[j] = __float2half_rn(ov);
    }
}

// all 5 layers' gate biases at once: g_bg[l][3072] = bd|bf|bi of layer l
__global__ void catbias(const float* __restrict__ bd, const float* __restrict__ bf,
                        const float* __restrict__ bi)
{
    int lin = blockIdx.x * 256 + threadIdx.x;      // < 5*3072
    if (lin >= (L_NUM - 1) * 3072) return;
    int l = lin / 3072, j = lin % 3072;
    float v;
    if (j < 1024)      v = bd[(size_t)l * C_DIM + j];
    else if (j < 2048) v = bf[(size_t)l * C_DIM + j - 1024];
    else               v = bi[(size_t)l * C_DIM + j - 2048];
    g_bg[lin] = v;
}

// ---------------------------------------------------------------------------
// Launch: conversions on a fork-join side stream (DRAM-bound now, overlaps
// the compute-bound GEMM stack; Wout conversion hides fully under 6 layers).
// ---------------------------------------------------------------------------
extern "C" void kernel_launch(void* const* d_in, const int* in_sizes, int n_in,
                              void* d_out, int out_size)
{
    (void)in_sizes; (void)n_in; (void)out_size;
    const int*   ids  = (const int*)d_in[0];
    const float* emb  = (const float*)d_in[1];
    const float* en_g = (const float*)d_in[2];
    const float* en_b = (const float*)d_in[3];
    const float* W1   = (const float*)d_in[4];
    const float* b1   = (const float*)d_in[5];
    const float* Wd   = (const float*)d_in[6];
    const float* bd   = (const float*)d_in[7];
    const float* Wf   = (const float*)d_in[8];
    const float* bf   = (const float*)d_in[9];
    const float* Wi   = (const float*)d_in[10];
    const float* bi   = (const float*)d_in[11];
    const float* lng  = (const float*)d_in[12];
    const float* lnb  = (const float*)d_in[13];
    const float* Wout = (const float*)d_in[14];
    const float* bout = (const float*)d_in[15];
    float* out = (float*)d_out;

    __half *W1T, *WgT, *WoutT, *xc, *hid;
    float *gates, *bg;
    cudaGetSymbolAddress((void**)&W1T, g_W1T);
    cudaGetSymbolAddress((void**)&WgT, g_WgT);
    cudaGetSymbolAddress((void**)&WoutT, g_WoutT);
    cudaGetSymbolAddress((void**)&xc, g_xc);
    cudaGetSymbolAddress((void**)&hid, g_hidden);
    cudaGetSymbolAddress((void**)&gates, g_gates);
    cudaGetSymbolAddress((void**)&bg, g_bg);

    cudaFuncSetAttribute(gemm_hmma, cudaFuncAttributeMaxDynamicSharedMemorySize, SMEM_GEMM);

    static cudaStream_t s2 = nullptr;
    static cudaEvent_t evFork = nullptr, evA = nullptr, evB = nullptr;
    if (s2 == nullptr) {
        cudaStreamCreateWithFlags(&s2, cudaStreamNonBlocking);
        cudaEventCreateWithFlags(&evFork, cudaEventDisableTiming);
        cudaEventCreateWithFlags(&evA, cudaEventDisableTiming);
        cudaEventCreateWithFlags(&evB, cudaEventDisableTiming);
    }

    // ---- fork side stream for ALL weight conversions ----
    cudaEventRecord(evFork, 0);
    cudaStreamWaitEvent(s2, evFork, 0);
    convT3<<<dim3(H_DIM / 64, 2048 / 64, L_NUM), 256, 0, s2>>>(
        W1, W1T, 2048, H_DIM, (size_t)2048 * H_DIM, (size_t)H_DIM * 2048, 1);
    conv_gatesT<<<dim3(C_DIM / 64, H_DIM / 64, 3 * (L_NUM - 1)), 256, 0, s2>>>(Wd, Wf, Wi);
    cudaEventRecord(evA, s2);
    convT3<<<dim3(V_DIM / 64, H_DIM / 64, 1), 256, 0, s2>>>(
        Wout, WoutT, H_DIM, V_DIM, 0, 0, 0);
    cudaEventRecord(evB, s2);

    // ---- main: prologue overlaps conversions ----
    catbias<<<60, 256>>>(bd, bf, bi);
    embed_ln_kernel<<<N_TOK, 256>>>(ids, emb, en_g, en_b);
    cudaStreamWaitEvent(0, evA, 0);   // W1 + gates must be converted

    dim3 gH(N_TOK / 128, H_DIM / 128);   // (32, 32)
    dim3 gG(N_TOK / 128, 3072 / 128);    // (32, 24)
    dim3 gV(N_TOK / 128, V_DIM / 128);   // (32, 250)

    for (int l = 0; l < L_NUM; l++) {
        int Keff = (l == 0) ? E_DIM : 2048;
        gemm_hmma<<<gH, 128, SMEM_GEMM>>>(
            xc, 2048, W1T + (size_t)l * H_DIM * 2048, 2048,
            b1 + (size_t)l * H_DIM, hid, H_DIM, Keff, 1);

        if (l < L_NUM - 1) {
            gemm_hmma<<<gG, 128, SMEM_GEMM>>>(
                hid, H_DIM, WgT + (size_t)l * 3072 * H_DIM, H_DIM,
                bg + (size_t)l * 3072, gates, 3072, H_DIM, 0);
            ctx_kernel<<<N_TOK, 256>>>(lng + (size_t)l * C_DIM, lnb + (size_t)l * C_DIM);
        }
    }

    cudaStreamWaitEvent(0, evB, 0);   // Wout conversion joins before head GEMM
    gemm_hmma<<<gV, 128, SMEM_GEMM>>>(hid, H_DIM, WoutT, H_DIM, bout, out, V_DIM, H_DIM, 0);
}